// round 12
// baseline (speedup 1.0000x reference)
#include <cuda_runtime.h>

#define NN 48000          // NUM_NODES * WINDOW
#define NODES 2000
#define WIN 24
#define EE 768000
#define EEPAD (EE + NN * 8)   // CSR capacity with per-row pad to multiple of 8
#define FIN 12
#define HID 64
#define NG 256            // 4 * LSTM_H gates
#define NB 14             // nodes per block in fused LSTM (143 blocks x 14 = 2002)
#define NBLK 143
#define NGRP1 3000        // NN / 16  (layer1 groups)
#define NGRP64 1500       // NN / 32  (layer64 groups)
#define NTILE 1500        // NN / 32  (xproj tiles, 32 rows each)
#define SIDX_CAP 3072     // layer64 smem index staging capacity (ints)
#define SIDX1_CAP 2048    // layer1 smem index staging capacity (ints)

typedef unsigned long long u64t;

// ---------------- packed f32x2 helpers (Blackwell) ---------------------------
__device__ __forceinline__ void ffma2(u64t &d, u64t a, u64t b) {
    asm("fma.rn.f32x2 %0, %1, %2, %0;" : "+l"(d) : "l"(a), "l"(b));
}
__device__ __forceinline__ u64t add2(u64t a, u64t b) {
    u64t r; asm("add.rn.f32x2 %0, %1, %2;" : "=l"(r) : "l"(a), "l"(b)); return r;
}
__device__ __forceinline__ u64t pack2(float lo, float hi) {
    u64t r; asm("mov.b64 %0, {%1, %2};" : "=l"(r) : "f"(lo), "f"(hi)); return r;
}
__device__ __forceinline__ float hsum2(u64t v) {
    float lo, hi; asm("mov.b64 {%0, %1}, %2;" : "=f"(lo), "=f"(hi) : "l"(v));
    return lo + hi;
}
__device__ __forceinline__ float2 unpack2(u64t v) {
    float lo, hi; asm("mov.b64 {%0, %1}, %2;" : "=f"(lo), "=f"(hi) : "l"(v));
    return make_float2(lo, hi);
}

// ---------------- scratch (device globals) -----------------------------------
// Row NN of g_xs / g_fA / g_fB is a sentinel row: NEVER written, stays zero
// (device globals are zero-initialized). CSR rows are padded to multiples of 8
// with index NN, so gathers have no tails and no bounds checks.
__device__ int   g_deg[NN];        // invariant: zero at kernel_launch entry
__device__ int   g_offs[NN];       // inclusive scan of PADDED degrees
__device__ int   g_cursor[NN];
__device__ float g_dinv[NN];
__device__ __align__(16) int g_csrc[EEPAD];
__device__ __align__(16) float g_xs[(NN + 1) * FIN];
__device__ __align__(16) float g_fA[(NN + 1) * HID];
__device__ __align__(16) float g_fB[(NN + 1) * HID];
__device__ __align__(16) float g_xp[NN * NG];
__device__ int g_bsum[256];

// ---------------- graph preprocessing (separate launches) --------------------
// 4 edges per thread: EE = 750 * 256 * 4 exactly, no bounds checks.
__global__ void __launch_bounds__(256) k_count(const int* __restrict__ ei) {
    int e0 = blockIdx.x * 1024 + threadIdx.x;
    int d0 = ei[EE + e0];
    int d1 = ei[EE + e0 + 256];
    int d2 = ei[EE + e0 + 512];
    int d3 = ei[EE + e0 + 768];
    atomicAdd(&g_deg[d0], 1);
    atomicAdd(&g_deg[d1], 1);
    atomicAdd(&g_deg[d2], 1);
    atomicAdd(&g_deg[d3], 1);
}
// per-chunk inclusive scan of PADDED degrees; chunk totals to g_bsum
__global__ void k_scanA() {
    __shared__ int s[256];
    int tid = threadIdx.x;
    int i = blockIdx.x * 256 + tid;
    int pd = 0;
    if (i < NN) pd = (g_deg[i] + 7) & ~7;
    s[tid] = pd;
    __syncthreads();
    for (int o = 1; o < 256; o <<= 1) {
        int t = (tid >= o) ? s[tid - o] : 0;
        __syncthreads();
        s[tid] += t;
        __syncthreads();
    }
    if (i < NN) g_offs[i] = s[tid];
    if (tid == 255) g_bsum[blockIdx.x] = s[255];
}
// chunk base (local reduction of g_bsum) + offs/cursor/sentinels/dinv/xs
__global__ void k_scanC(const float* __restrict__ x) {
    __shared__ int s[256];
    int b = blockIdx.x, tid = threadIdx.x;
    int v = (tid < b) ? g_bsum[tid] : 0;   // b <= 187 < 256
    s[tid] = v;
    __syncthreads();
    for (int o = 128; o > 0; o >>= 1) {
        if (tid < o) s[tid] += s[tid + o];
        __syncthreads();
    }
    int base = s[0];
    int i = b * 256 + tid;
    if (i < NN) {
        int dg = g_deg[i];
        int pd = (dg + 7) & ~7;
        int off = g_offs[i] + base;       // end of this row (padded)
        int start = off - pd;
        g_offs[i] = off;
        g_cursor[i] = start;
        for (int k = dg; k < pd; k++) g_csrc[start + k] = NN;   // sentinels
        float di = rsqrtf((float)dg + 1.0f);
        g_dinv[i] = di;
#pragma unroll
        for (int f = 0; f < FIN; f++) g_xs[i * FIN + f] = x[i * FIN + f] * di;
    }
}
// 4 edges per thread: batched loads -> 4 independent cursor atomics -> stores
__global__ void __launch_bounds__(256) k_fill(const int* __restrict__ ei) {
    int e0 = blockIdx.x * 1024 + threadIdx.x;
    int s0 = ei[e0];
    int s1 = ei[e0 + 256];
    int s2 = ei[e0 + 512];
    int s3 = ei[e0 + 768];
    int d0 = ei[EE + e0];
    int d1 = ei[EE + e0 + 256];
    int d2 = ei[EE + e0 + 512];
    int d3 = ei[EE + e0 + 768];
    int p0 = atomicAdd(&g_cursor[d0], 1);
    int p1 = atomicAdd(&g_cursor[d1], 1);
    int p2 = atomicAdd(&g_cursor[d2], 1);
    int p3 = atomicAdd(&g_cursor[d3], 1);
    g_csrc[p0] = s0;
    g_csrc[p1] = s1;
    g_csrc[p2] = s2;
    g_csrc[p3] = s3;
}

// ---------------- layer 1: fused 12-wide aggregate + 12->64 GEMM -------------
// Indices for the group's 16 contiguous CSR rows staged in smem (as in layer64).
__global__ void __launch_bounds__(256) k_layer1(const float* __restrict__ W1,
                                                const float* __restrict__ b1) {
    __shared__ float sW[FIN * 64];
    __shared__ float sb[64];
    __shared__ float sU[16 * FIN];
    __shared__ __align__(16) int sidx[SIDX1_CAP];
    int tid = threadIdx.x;
    int w = tid >> 5, lane = tid & 31;
    int sub = lane >> 4, f = lane & 15;
    for (int i = tid; i < FIN * 64; i += 256) sW[i] = W1[i];
    if (tid < 64) sb[tid] = b1[tid];
    __syncthreads();

#pragma unroll 1
    for (int grp = blockIdx.x; grp < NGRP1; grp += gridDim.x) {
        int g0 = grp * 16;
        // stage indices for rows g0..g0+15 (contiguous in padded CSR)
        int start0 = g_offs[g0] - ((g_deg[g0] + 7) & ~7);
        int endL = g_offs[g0 + 15];
        int L = endL - start0;
        bool use_s = (L <= SIDX1_CAP);
        if (use_s) {
#pragma unroll 1
            for (int i = tid * 4; i < L; i += 1024)
                *(int4*)&sidx[i] = *(const int4*)&g_csrc[start0 + i];
        }
        __syncthreads();
        const int* ip = use_s ? (const int*)sidx - start0 : (const int*)g_csrc;
        {
            int m = w * 2 + sub;
            int d = g0 + m;
            if (f < FIN) {
                int dg = g_deg[d];
                int pd = (dg + 7) & ~7;
                int end = g_offs[d];
                float acc = 0.f;
#pragma unroll 1
                for (int e = end - pd; e < end; e += 4) {
                    int4 iv = *(const int4*)&ip[e];
                    acc += g_xs[iv.x * FIN + f] + g_xs[iv.y * FIN + f]
                         + g_xs[iv.z * FIN + f] + g_xs[iv.w * FIN + f];
                }
                acc += g_xs[d * FIN + f];
                sU[m * FIN + f] = g_dinv[d] * acc;
            }
        }
        __syncthreads();
        {
            int c4 = (tid & 15) * 4;
            int m = tid >> 4;
            float4 acc = make_float4(sb[c4], sb[c4 + 1], sb[c4 + 2], sb[c4 + 3]);
#pragma unroll
            for (int k = 0; k < FIN; k++) {
                float a = sU[m * FIN + k];
                float4 wv = *(float4*)&sW[k * 64 + c4];
                acc.x += a * wv.x; acc.y += a * wv.y; acc.z += a * wv.z; acc.w += a * wv.w;
            }
            float s = g_dinv[g0 + m];
            float4 r;
            r.x = fmaxf(acc.x, 0.f) * s;
            r.y = fmaxf(acc.y, 0.f) * s;
            r.z = fmaxf(acc.z, 0.f) * s;
            r.w = fmaxf(acc.w, 0.f) * s;
            *(float4*)&g_fA[(g0 + m) * 64 + c4] = r;
        }
        __syncthreads();
    }
}

// ---------------- fused 64-wide aggregate + 64x64 GEMM (32 dsts/grp) ---------
// Group's CSR indices staged in smem; gather index fetch is LDS, feature
// gathers have 32 loads in flight per warp.
// SRCA: read g_fA else g_fB (write the other). SCALE: scale output by dinv.
// SCALE=false (last layer) also zeroes g_deg per group after its final read.
template <bool SRCA, bool SCALE>
__global__ void __launch_bounds__(256) k_layer64(const float* __restrict__ W,
                                                 const float* __restrict__ b) {
    __shared__ float sW[4096];
    __shared__ float sb[64];
    __shared__ __align__(16) float sA[2048];
    __shared__ __align__(16) int sidx[SIDX_CAP];
    const float* __restrict__ src = SRCA ? g_fA : g_fB;
    float* __restrict__ dst = SRCA ? g_fB : g_fA;
    int tid = threadIdx.x;
    int w = tid >> 5, lane = tid & 31;
    for (int i = tid; i < 4096; i += 256) sW[i] = W[i];
    if (tid < 64) sb[tid] = b[tid];
    __syncthreads();

#pragma unroll 1
    for (int grp = blockIdx.x; grp < NGRP64; grp += gridDim.x) {
        int g0 = grp * 32;
        // stage indices: [start0, endL) is the contiguous padded CSR range
        int start0 = g_offs[g0] - ((g_deg[g0] + 7) & ~7);
        int endL = g_offs[g0 + 31];
        int L = endL - start0;                 // multiple of 8, 32B-aligned base
        bool use_s = (L <= SIDX_CAP);          // uniform across block
        if (use_s) {
#pragma unroll 1
            for (int i = tid * 4; i < L; i += 1024)
                *(int4*)&sidx[i] = *(const int4*)&g_csrc[start0 + i];
        }
        __syncthreads();
        const int* ip = use_s ? (const int*)sidx - start0 : (const int*)g_csrc;
        // gather: warp handles 4 dsts, 8 edges per dst per round
        {
            int d[4]; int e[4], en[4]; u64t acc[4];
#pragma unroll
            for (int p = 0; p < 4; p++) {
                d[p] = g0 + w + p * 8;
                en[p] = g_offs[d[p]];
                int pd = (g_deg[d[p]] + 7) & ~7;
                e[p] = en[p] - pd;
                acc[p] = 0ULL;
            }
#pragma unroll 1
            for (;;) {
                bool any = false;
#pragma unroll
                for (int p = 0; p < 4; p++) {
                    if (e[p] < en[p]) {
                        any = true;
                        int4 i0 = *(const int4*)&ip[e[p]];
                        int4 i1 = *(const int4*)&ip[e[p] + 4];
                        u64t v0 = *(const u64t*)&src[i0.x * 64 + lane * 2];
                        u64t v1 = *(const u64t*)&src[i0.y * 64 + lane * 2];
                        u64t v2 = *(const u64t*)&src[i0.z * 64 + lane * 2];
                        u64t v3 = *(const u64t*)&src[i0.w * 64 + lane * 2];
                        u64t v4 = *(const u64t*)&src[i1.x * 64 + lane * 2];
                        u64t v5 = *(const u64t*)&src[i1.y * 64 + lane * 2];
                        u64t v6 = *(const u64t*)&src[i1.z * 64 + lane * 2];
                        u64t v7 = *(const u64t*)&src[i1.w * 64 + lane * 2];
                        acc[p] = add2(acc[p],
                                 add2(add2(add2(v0, v1), add2(v2, v3)),
                                      add2(add2(v4, v5), add2(v6, v7))));
                        e[p] += 8;
                    }
                }
                if (!any) break;
            }
#pragma unroll
            for (int p = 0; p < 4; p++) {
                acc[p] = add2(acc[p], *(const u64t*)&src[d[p] * 64 + lane * 2]);
                float2 r = unpack2(acc[p]);
                float di = g_dinv[d[p]];
                sA[(w + p * 8) * 64 + lane * 2]     = di * r.x;
                sA[(w + p * 8) * 64 + lane * 2 + 1] = di * r.y;
            }
        }
        __syncthreads();
        if (!SCALE) {                     // last layer: restore deg==0 invariant
            if (tid < 32) g_deg[g0 + tid] = 0;
        }
        // GEMM 32x64 @ 64x64 + bias + relu (+dinv) — 8 outputs/thread
        {
            int c4 = (tid & 15) * 4;
            int m = tid >> 4;                  // rows m and m+16
            float4 acc0 = make_float4(sb[c4], sb[c4 + 1], sb[c4 + 2], sb[c4 + 3]);
            float4 acc1 = acc0;
#pragma unroll
            for (int k4 = 0; k4 < 16; k4++) {
                float4 a0 = *(float4*)&sA[m * 64 + k4 * 4];
                float4 a1 = *(float4*)&sA[(m + 16) * 64 + k4 * 4];
                float4 wv;
                wv = *(float4*)&sW[(k4 * 4 + 0) * 64 + c4];
                acc0.x += a0.x * wv.x; acc0.y += a0.x * wv.y; acc0.z += a0.x * wv.z; acc0.w += a0.x * wv.w;
                acc1.x += a1.x * wv.x; acc1.y += a1.x * wv.y; acc1.z += a1.x * wv.z; acc1.w += a1.x * wv.w;
                wv = *(float4*)&sW[(k4 * 4 + 1) * 64 + c4];
                acc0.x += a0.y * wv.x; acc0.y += a0.y * wv.y; acc0.z += a0.y * wv.z; acc0.w += a0.y * wv.w;
                acc1.x += a1.y * wv.x; acc1.y += a1.y * wv.y; acc1.z += a1.y * wv.z; acc1.w += a1.y * wv.w;
                wv = *(float4*)&sW[(k4 * 4 + 2) * 64 + c4];
                acc0.x += a0.z * wv.x; acc0.y += a0.z * wv.y; acc0.z += a0.z * wv.z; acc0.w += a0.z * wv.w;
                acc1.x += a1.z * wv.x; acc1.y += a1.z * wv.y; acc1.z += a1.z * wv.z; acc1.w += a1.z * wv.w;
                wv = *(float4*)&sW[(k4 * 4 + 3) * 64 + c4];
                acc0.x += a0.w * wv.x; acc0.y += a0.w * wv.y; acc0.z += a0.w * wv.z; acc0.w += a0.w * wv.w;
                acc1.x += a1.w * wv.x; acc1.y += a1.w * wv.y; acc1.z += a1.w * wv.z; acc1.w += a1.w * wv.w;
            }
            float s0 = SCALE ? g_dinv[g0 + m] : 1.f;
            float s1 = SCALE ? g_dinv[g0 + m + 16] : 1.f;
            float4 r0, r1;
            r0.x = fmaxf(acc0.x, 0.f) * s0; r0.y = fmaxf(acc0.y, 0.f) * s0;
            r0.z = fmaxf(acc0.z, 0.f) * s0; r0.w = fmaxf(acc0.w, 0.f) * s0;
            r1.x = fmaxf(acc1.x, 0.f) * s1; r1.y = fmaxf(acc1.y, 0.f) * s1;
            r1.z = fmaxf(acc1.z, 0.f) * s1; r1.w = fmaxf(acc1.w, 0.f) * s1;
            *(float4*)&dst[(g0 + m) * 64 + c4] = r0;
            *(float4*)&dst[(g0 + m + 16) * 64 + c4] = r1;
        }
        __syncthreads();
    }
}

// ---------------- LSTM layer-0 input projection: outer-product tiling --------
// Tile = 32 rows x 256 gates; thread computes 8 rows x 4 gates (2 gate-pairs).
#define WGP_STRIDE 65
__global__ void __launch_bounds__(256) k_xproj(const float* __restrict__ Wih,
                                               const float* __restrict__ bih,
                                               const float* __restrict__ bhh) {
    extern __shared__ __align__(16) char smraw[];
    u64t* sWgp  = (u64t*)smraw;                  // 128 * 65 = 8320 u64t
    u64t* sxdup = sWgp + 128 * WGP_STRIDE;       // 32 * 64 = 2048 u64t
    u64t* sBgp  = sxdup + 2048;                  // 128 u64t
    int tid = threadIdx.x;
    int gq = tid & 63;        // gate-quad: gates 4gq..4gq+3
    int rq = tid >> 6;        // row-octet: rows 8rq..8rq+7

    for (int i = tid; i < 128 * 64; i += 256) {
        int gp = i >> 6, j = i & 63;
        sWgp[gp * WGP_STRIDE + j] = pack2(Wih[(2 * gp) * 64 + j], Wih[(2 * gp + 1) * 64 + j]);
    }
    if (tid < 128)
        sBgp[tid] = pack2(bih[2 * tid] + bhh[2 * tid], bih[2 * tid + 1] + bhh[2 * tid + 1]);
    __syncthreads();

    const u64t* wrow0 = &sWgp[(2 * gq) * WGP_STRIDE];       // 16B-aligned rows
    const u64t* wrow1 = &sWgp[(2 * gq + 1) * WGP_STRIDE];   // 8B-aligned only
    u64t bg0 = sBgp[2 * gq], bg1 = sBgp[2 * gq + 1];

#pragma unroll 1
    for (int tile = blockIdx.x; tile < NTILE; tile += gridDim.x) {
        int g0 = tile * 32;
#pragma unroll
        for (int k = 0; k < 2; k++) {
            int i4 = tid + k * 256;           // 512 float4 total
            int r = i4 >> 4, j4 = i4 & 15;
            float4 v = *(const float4*)&g_fB[(g0 + r) * 64 + j4 * 4];
            sxdup[r * 64 + j4 * 4 + 0] = pack2(v.x, v.x);
            sxdup[r * 64 + j4 * 4 + 1] = pack2(v.y, v.y);
            sxdup[r * 64 + j4 * 4 + 2] = pack2(v.z, v.z);
            sxdup[r * 64 + j4 * 4 + 3] = pack2(v.w, v.w);
        }
        __syncthreads();
        u64t acc[8][2];
#pragma unroll
        for (int r = 0; r < 8; r++) { acc[r][0] = bg0; acc[r][1] = bg1; }
#pragma unroll 4
        for (int j2 = 0; j2 < 32; j2++) {
            ulonglong2 w0 = *(const ulonglong2*)&wrow0[j2 * 2];   // aligned
            u64t w1x = wrow1[j2 * 2];                             // LDS.64 pair
            u64t w1y = wrow1[j2 * 2 + 1];
#pragma unroll
            for (int r = 0; r < 8; r++) {
                ulonglong2 xv = *(const ulonglong2*)&sxdup[(8 * rq + r) * 64 + j2 * 2];
                ffma2(acc[r][0], w0.x, xv.x);
                ffma2(acc[r][0], w0.y, xv.y);
                ffma2(acc[r][1], w1x, xv.x);
                ffma2(acc[r][1], w1y, xv.y);
            }
        }
        u64t* outp = (u64t*)g_xp;
#pragma unroll
        for (int r = 0; r < 8; r++) {
            ulonglong2 st;
            st.x = acc[r][0]; st.y = acc[r][1];
            *(ulonglong2*)&outp[(u64t)(g0 + 8 * rq + r) * 128 + 2 * gq] = st;
        }
        __syncthreads();
    }
}

// ---------------- fused 2-layer LSTM + output projection (NB=14/block) ------
__device__ __forceinline__ float sigf(float x) { return 1.f / (1.f + __expf(-x)); }
__device__ __forceinline__ float tanhfast(float x) { return 1.f - 2.f / (__expf(2.f * x) + 1.f); }

__global__ void __launch_bounds__(256, 1) k_lstm(
    const float* __restrict__ Whh0,
    const float* __restrict__ Wih1, const float* __restrict__ Whh1,
    const float* __restrict__ bih1, const float* __restrict__ bhh1,
    const float* __restrict__ Wout, const float* __restrict__ bout,
    float* __restrict__ out)
{
    extern __shared__ float sm[];
    float* sW0  = sm;                  // 16384
    float* sWi1 = sm + 16384;          // 16384
    float* sW1  = sm + 32768;          // 16384
    float* sh0  = sm + 49152;          // NB*64 = 896
    float* sh1  = sh0 + NB * 64;       // 896
    float* sg   = sh1 + NB * 64;       // NB*256 = 3584
    float* sB1  = sg + NB * 256;       // 256

    int tid = threadIdx.x;
    for (int i = tid; i < NG * HID; i += 256) {
        int r = i >> 6, c = i & 63;
        int pos = r * 64 + (((c >> 2) ^ (r & 15)) << 2) + (c & 3);
        sW0[pos]  = Whh0[i];
        sWi1[pos] = Wih1[i];
        sW1[pos]  = Whh1[i];
    }
    sB1[tid] = bih1[tid] + bhh1[tid];
    for (int i = tid; i < NB * 64; i += 256) { sh0[i] = 0.f; sh1[i] = 0.f; }
    int gtype = tid >> 6;   // 0:i 1:f 2:g 3:o
    int wbase = tid * 64;
    int wrot  = tid & 15;
    __syncthreads();
    u64t b1p = pack2(sB1[tid], 0.f);

    int n0 = blockIdx.x * NB;
    float c0[4] = {0.f, 0.f, 0.f, 0.f};
    float c1[4] = {0.f, 0.f, 0.f, 0.f};

#pragma unroll 1
    for (int t = 0; t < WIN; t++) {
        // ---- layer 0 gates ----
        u64t acc[NB];
#pragma unroll
        for (int nn = 0; nn < NB; nn++) {
            int n = n0 + nn;
            int nc = (n < NODES) ? n : (NODES - 1);
            acc[nn] = pack2(g_xp[(t * NODES + nc) * NG + tid], 0.f);
        }
#pragma unroll 8
        for (int j4 = 0; j4 < 16; j4++) {
            ulonglong2 wv = *(const ulonglong2*)&sW0[wbase + ((j4 ^ wrot) << 2)];
#pragma unroll
            for (int nn = 0; nn < NB; nn++) {
                ulonglong2 h = *(const ulonglong2*)&sh0[nn * 64 + j4 * 4];
                ffma2(acc[nn], wv.x, h.x);
                ffma2(acc[nn], wv.y, h.y);
            }
        }
#pragma unroll
        for (int nn = 0; nn < NB; nn++) {
            float v = hsum2(acc[nn]);
            sg[nn * 256 + tid] = (gtype == 2) ? tanhfast(v) : sigf(v);
        }
        __syncthreads();
#pragma unroll
        for (int r = 0; r < 4; r++) {
            int idx = tid + 256 * r;
            if (idx < NB * 64) {
                int nn = idx >> 6, e = idx & 63;
                float gi = sg[nn * 256 + e],       gf = sg[nn * 256 + 64 + e];
                float gg = sg[nn * 256 + 128 + e], go = sg[nn * 256 + 192 + e];
                c0[r] = gf * c0[r] + gi * gg;
                sh0[idx] = go * tanhfast(c0[r]);
            }
        }
        __syncthreads();
        // ---- layer 1 gates ----
#pragma unroll
        for (int nn = 0; nn < NB; nn++) acc[nn] = b1p;
#pragma unroll 8
        for (int j4 = 0; j4 < 16; j4++) {
            int wo = (j4 ^ wrot) << 2;
            ulonglong2 wi = *(const ulonglong2*)&sWi1[wbase + wo];
            ulonglong2 wh = *(const ulonglong2*)&sW1[wbase + wo];
#pragma unroll
            for (int nn = 0; nn < NB; nn++) {
                ulonglong2 h0 = *(const ulonglong2*)&sh0[nn * 64 + j4 * 4];
                ulonglong2 h1 = *(const ulonglong2*)&sh1[nn * 64 + j4 * 4];
                ffma2(acc[nn], wi.x, h0.x);
                ffma2(acc[nn], wi.y, h0.y);
                ffma2(acc[nn], wh.x, h1.x);
                ffma2(acc[nn], wh.y, h1.y);
            }
        }
#pragma unroll
        for (int nn = 0; nn < NB; nn++) {
            float v = hsum2(acc[nn]);
            sg[nn * 256 + tid] = (gtype == 2) ? tanhfast(v) : sigf(v);
        }
        __syncthreads();
#pragma unroll
        for (int r = 0; r < 4; r++) {
            int idx = tid + 256 * r;
            if (idx < NB * 64) {
                int nn = idx >> 6, e = idx & 63;
                float gi = sg[nn * 256 + e],       gf = sg[nn * 256 + 64 + e];
                float gg = sg[nn * 256 + 128 + e], go = sg[nn * 256 + 192 + e];
                c1[r] = gf * c1[r] + gi * gg;
                sh1[idx] = go * tanhfast(c1[r]);
            }
        }
        __syncthreads();
    }
    // ---- output projection: 14 nodes x 96 outputs ----
#pragma unroll 1
    for (int i = tid; i < NB * 96; i += 256) {
        int nn = i / 96, o = i - nn * 96;
        int n = n0 + nn;
        if (n < NODES) {
            float a = bout[o];
#pragma unroll
            for (int k = 0; k < 64; k++)
                a += sh1[nn * 64 + k] * Wout[k * 96 + o];
            out[n * 96 + o] = a;
        }
    }
}

// ---------------- launcher ---------------------------------------------------
extern "C" void kernel_launch(void* const* d_in, const int* in_sizes, int n_in,
                              void* d_out, int out_size) {
    const float* x    = (const float*)d_in[0];
    const int*   ei   = (const int*)  d_in[1];
    const float* W1   = (const float*)d_in[2];
    const float* b1   = (const float*)d_in[3];
    const float* W2   = (const float*)d_in[4];
    const float* b2   = (const float*)d_in[5];
    const float* W3   = (const float*)d_in[6];
    const float* b3   = (const float*)d_in[7];
    const float* W4   = (const float*)d_in[8];
    const float* b4   = (const float*)d_in[9];
    const float* Wih0 = (const float*)d_in[10];
    const float* Whh0 = (const float*)d_in[11];
    const float* bih0 = (const float*)d_in[12];
    const float* bhh0 = (const float*)d_in[13];
    const float* Wih1 = (const float*)d_in[14];
    const float* Whh1 = (const float*)d_in[15];
    const float* bih1 = (const float*)d_in[16];
    const float* bhh1 = (const float*)d_in[17];
    const float* Wout = (const float*)d_in[18];
    const float* bout = (const float*)d_in[19];
    float* out = (float*)d_out;

    const int XP_SMEM   = (128 * WGP_STRIDE + 2048 + 128) * 8;                // 83968
    const int LSTM_SMEM = (3 * 16384 + NB * 64 * 2 + NB * 256 + 256) * 4;     // 219136
    cudaFuncSetAttribute(k_xproj, cudaFuncAttributeMaxDynamicSharedMemorySize, XP_SMEM);
    cudaFuncSetAttribute(k_lstm,  cudaFuncAttributeMaxDynamicSharedMemorySize, LSTM_SMEM);

    // graph preprocessing (separate launches; g_deg zeroed by last GCN layer)
    k_count<<<750, 256>>>(ei);
    k_scanA<<<188, 256>>>();
    k_scanC<<<188, 256>>>(x);
    k_fill<<<750, 256>>>(ei);

    // GCN stack (fused aggregate + GEMM, double-buffered A/B)
    k_layer1<<<750, 256>>>(W1, b1);                  // xs -> A
    k_layer64<true,  true ><<<750, 256>>>(W2, b2);   // A -> B
    k_layer64<false, true ><<<750, 256>>>(W3, b3);   // B -> A
    k_layer64<true,  false><<<750, 256>>>(W4, b4);   // A -> B (unscaled; zeroes g_deg)

    // LSTM
    k_xproj<<<750, 256, XP_SMEM>>>(Wih0, bih0, bhh0);
    k_lstm<<<NBLK, 256, LSTM_SMEM>>>(Whh0, Wih1, Whh1, bih1, bhh1, Wout, bout, out);
}

// round 13
// speedup vs baseline: 1.0006x; 1.0006x over previous
#include <cuda_runtime.h>

#define NN 48000          // NUM_NODES * WINDOW
#define NODES 2000
#define WIN 24
#define EE 768000
#define EEPAD (EE + NN * 8)   // CSR capacity with per-row pad to multiple of 8
#define FIN 12
#define HID 64
#define NG 256            // 4 * LSTM_H gates
#define NB 14             // nodes per block in fused LSTM (143 blocks x 14 = 2002)
#define NBLK 143
#define NGRP1 3000        // NN / 16  (layer1 groups)
#define NGRP64 750        // NN / 64  (layer64 groups, one per block)
#define NTILE 1500        // NN / 32  (xproj tiles, 32 rows each)
#define SIDX_CAP 3072     // layer64 smem index staging capacity (ints)

typedef unsigned long long u64t;

// ---------------- packed f32x2 helpers (Blackwell) ---------------------------
__device__ __forceinline__ void ffma2(u64t &d, u64t a, u64t b) {
    asm("fma.rn.f32x2 %0, %1, %2, %0;" : "+l"(d) : "l"(a), "l"(b));
}
__device__ __forceinline__ u64t add2(u64t a, u64t b) {
    u64t r; asm("add.rn.f32x2 %0, %1, %2;" : "=l"(r) : "l"(a), "l"(b)); return r;
}
__device__ __forceinline__ u64t pack2(float lo, float hi) {
    u64t r; asm("mov.b64 %0, {%1, %2};" : "=l"(r) : "f"(lo), "f"(hi)); return r;
}
__device__ __forceinline__ float hsum2(u64t v) {
    float lo, hi; asm("mov.b64 {%0, %1}, %2;" : "=f"(lo), "=f"(hi) : "l"(v));
    return lo + hi;
}
__device__ __forceinline__ float2 unpack2(u64t v) {
    float lo, hi; asm("mov.b64 {%0, %1}, %2;" : "=f"(lo), "=f"(hi) : "l"(v));
    return make_float2(lo, hi);
}

// ---------------- scratch (device globals) -----------------------------------
// Row NN of g_xs / g_fA / g_fB is a sentinel row: NEVER written, stays zero
// (device globals are zero-initialized). CSR rows are padded to multiples of 8
// with index NN, so gathers have no tails and no bounds checks.
__device__ int   g_deg[NN];        // invariant: zero at kernel_launch entry
__device__ int   g_offs[NN];       // inclusive scan of PADDED degrees
__device__ int   g_cursor[NN];
__device__ float g_dinv[NN];
__device__ __align__(16) int g_csrc[EEPAD];
__device__ __align__(16) float g_xs[(NN + 1) * FIN];
__device__ __align__(16) float g_fA[(NN + 1) * HID];
__device__ __align__(16) float g_fB[(NN + 1) * HID];
__device__ __align__(16) float g_xp[NN * NG];
__device__ int g_bsum[256];

// ---------------- graph preprocessing (separate launches) --------------------
__global__ void k_count(const int* __restrict__ ei) {
    int e = blockIdx.x * 256 + threadIdx.x;
    if (e < EE) atomicAdd(&g_deg[ei[EE + e]], 1);
}
// per-chunk inclusive scan of PADDED degrees; chunk totals to g_bsum
__global__ void k_scanA() {
    __shared__ int s[256];
    int tid = threadIdx.x;
    int i = blockIdx.x * 256 + tid;
    int pd = 0;
    if (i < NN) pd = (g_deg[i] + 7) & ~7;
    s[tid] = pd;
    __syncthreads();
    for (int o = 1; o < 256; o <<= 1) {
        int t = (tid >= o) ? s[tid - o] : 0;
        __syncthreads();
        s[tid] += t;
        __syncthreads();
    }
    if (i < NN) g_offs[i] = s[tid];
    if (tid == 255) g_bsum[blockIdx.x] = s[255];
}
// chunk base (local reduction of g_bsum) + offs/cursor/sentinels/dinv/xs
__global__ void k_scanC(const float* __restrict__ x) {
    __shared__ int s[256];
    int b = blockIdx.x, tid = threadIdx.x;
    int v = (tid < b) ? g_bsum[tid] : 0;   // b <= 187 < 256
    s[tid] = v;
    __syncthreads();
    for (int o = 128; o > 0; o >>= 1) {
        if (tid < o) s[tid] += s[tid + o];
        __syncthreads();
    }
    int base = s[0];
    int i = b * 256 + tid;
    if (i < NN) {
        int dg = g_deg[i];
        int pd = (dg + 7) & ~7;
        int off = g_offs[i] + base;       // end of this row (padded)
        int start = off - pd;
        g_offs[i] = off;
        g_cursor[i] = start;
        for (int k = dg; k < pd; k++) g_csrc[start + k] = NN;   // sentinels
        float di = rsqrtf((float)dg + 1.0f);
        g_dinv[i] = di;
#pragma unroll
        for (int f = 0; f < FIN; f++) g_xs[i * FIN + f] = x[i * FIN + f] * di;
    }
}
__global__ void k_fill(const int* __restrict__ ei) {
    int e = blockIdx.x * 256 + threadIdx.x;
    if (e < EE) {
        int sn = ei[e];
        int d = ei[EE + e];
        int p = atomicAdd(&g_cursor[d], 1);
        g_csrc[p] = sn;
    }
}

// ---------------- layer 1: fused 12-wide aggregate + 12->64 GEMM -------------
__global__ void __launch_bounds__(256) k_layer1(const float* __restrict__ W1,
                                                const float* __restrict__ b1) {
    __shared__ float sW[FIN * 64];
    __shared__ float sb[64];
    __shared__ float sU[16 * FIN];
    int tid = threadIdx.x;
    int w = tid >> 5, lane = tid & 31;
    int sub = lane >> 4, f = lane & 15;
    for (int i = tid; i < FIN * 64; i += 256) sW[i] = W1[i];
    if (tid < 64) sb[tid] = b1[tid];
    __syncthreads();

#pragma unroll 1
    for (int grp = blockIdx.x; grp < NGRP1; grp += gridDim.x) {
        int g0 = grp * 16;
        {
            int m = w * 2 + sub;
            int d = g0 + m;
            if (f < FIN) {
                int dg = g_deg[d];
                int pd = (dg + 7) & ~7;
                int end = g_offs[d];
                float acc = 0.f;
#pragma unroll 1
                for (int e = end - pd; e < end; e += 4) {
                    int4 iv = *(const int4*)&g_csrc[e];
                    acc += g_xs[iv.x * FIN + f] + g_xs[iv.y * FIN + f]
                         + g_xs[iv.z * FIN + f] + g_xs[iv.w * FIN + f];
                }
                acc += g_xs[d * FIN + f];
                sU[m * FIN + f] = g_dinv[d] * acc;
            }
        }
        __syncthreads();
        {
            int c4 = (tid & 15) * 4;
            int m = tid >> 4;
            float4 acc = make_float4(sb[c4], sb[c4 + 1], sb[c4 + 2], sb[c4 + 3]);
#pragma unroll
            for (int k = 0; k < FIN; k++) {
                float a = sU[m * FIN + k];
                float4 wv = *(float4*)&sW[k * 64 + c4];
                acc.x += a * wv.x; acc.y += a * wv.y; acc.z += a * wv.z; acc.w += a * wv.w;
            }
            float s = g_dinv[g0 + m];
            float4 r;
            r.x = fmaxf(acc.x, 0.f) * s;
            r.y = fmaxf(acc.y, 0.f) * s;
            r.z = fmaxf(acc.z, 0.f) * s;
            r.w = fmaxf(acc.w, 0.f) * s;
            *(float4*)&g_fA[(g0 + m) * 64 + c4] = r;
        }
        __syncthreads();
    }
}

// ---------------- fused 64-wide aggregate + 64x64 GEMM (64 dsts/block) -------
// One group of 64 contiguous dsts per block. Each warp gathers 8 dsts (two
// 4-dst passes, 32 feature loads in flight) — sum-of-8 degree smoothing cuts
// the barrier-straggler overhead vs 4 dsts. CSR indices staged in smem.
// SRCA: read g_fA else g_fB (write the other). SCALE: scale output by dinv.
// SCALE=false (last layer) also zeroes g_deg per group after its final read.
template <bool SRCA, bool SCALE>
__global__ void __launch_bounds__(256) k_layer64(const float* __restrict__ W,
                                                 const float* __restrict__ b) {
    __shared__ float sW[4096];
    __shared__ float sb[64];
    __shared__ __align__(16) float sA[4096];
    __shared__ __align__(16) int sidx[SIDX_CAP];
    const float* __restrict__ src = SRCA ? g_fA : g_fB;
    float* __restrict__ dst = SRCA ? g_fB : g_fA;
    int tid = threadIdx.x;
    int w = tid >> 5, lane = tid & 31;
    for (int i = tid; i < 4096; i += 256) sW[i] = W[i];
    if (tid < 64) sb[tid] = b[tid];

    int g0 = blockIdx.x * 64;
    // stage indices: [start0, endL) is the contiguous padded CSR range
    int start0 = g_offs[g0] - ((g_deg[g0] + 7) & ~7);
    int endL = g_offs[g0 + 63];
    int L = endL - start0;                 // multiple of 8, 32B-aligned base
    bool use_s = (L <= SIDX_CAP);          // uniform across block
    if (use_s) {
#pragma unroll 1
        for (int i = tid * 4; i < L; i += 1024)
            *(int4*)&sidx[i] = *(const int4*)&g_csrc[start0 + i];
    }
    __syncthreads();
    const int* ip = use_s ? (const int*)sidx - start0 : (const int*)g_csrc;

    // gather: warp owns dsts {w + 8k, k=0..7}; two passes of 4 dsts each
#pragma unroll 1
    for (int half = 0; half < 2; half++) {
        int d[4]; int e[4], en[4]; u64t acc[4];
#pragma unroll
        for (int p = 0; p < 4; p++) {
            d[p] = g0 + w + (half * 4 + p) * 8;
            en[p] = g_offs[d[p]];
            int pd = (g_deg[d[p]] + 7) & ~7;
            e[p] = en[p] - pd;
            acc[p] = 0ULL;
        }
#pragma unroll 1
        for (;;) {
            bool any = false;
#pragma unroll
            for (int p = 0; p < 4; p++) {
                if (e[p] < en[p]) {
                    any = true;
                    int4 i0 = *(const int4*)&ip[e[p]];
                    int4 i1 = *(const int4*)&ip[e[p] + 4];
                    u64t v0 = *(const u64t*)&src[i0.x * 64 + lane * 2];
                    u64t v1 = *(const u64t*)&src[i0.y * 64 + lane * 2];
                    u64t v2 = *(const u64t*)&src[i0.z * 64 + lane * 2];
                    u64t v3 = *(const u64t*)&src[i0.w * 64 + lane * 2];
                    u64t v4 = *(const u64t*)&src[i1.x * 64 + lane * 2];
                    u64t v5 = *(const u64t*)&src[i1.y * 64 + lane * 2];
                    u64t v6 = *(const u64t*)&src[i1.z * 64 + lane * 2];
                    u64t v7 = *(const u64t*)&src[i1.w * 64 + lane * 2];
                    acc[p] = add2(acc[p],
                             add2(add2(add2(v0, v1), add2(v2, v3)),
                                  add2(add2(v4, v5), add2(v6, v7))));
                    e[p] += 8;
                }
            }
            if (!any) break;
        }
#pragma unroll
        for (int p = 0; p < 4; p++) {
            acc[p] = add2(acc[p], *(const u64t*)&src[d[p] * 64 + lane * 2]);
            float2 r = unpack2(acc[p]);
            float di = g_dinv[d[p]];
            int row = w + (half * 4 + p) * 8;
            sA[row * 64 + lane * 2]     = di * r.x;
            sA[row * 64 + lane * 2 + 1] = di * r.y;
        }
    }
    __syncthreads();
    if (!SCALE) {                     // last layer: restore deg==0 invariant
        if (tid < 64) g_deg[g0 + tid] = 0;
    }
    // GEMM 64x64 @ 64x64 + bias + relu (+dinv) — 16 outputs/thread
    {
        int c4 = (tid & 15) * 4;
        int m = tid >> 4;                  // rows m, m+16, m+32, m+48
        float4 a0 = make_float4(sb[c4], sb[c4 + 1], sb[c4 + 2], sb[c4 + 3]);
        float4 acc[4] = {a0, a0, a0, a0};
#pragma unroll
        for (int k4 = 0; k4 < 16; k4++) {
            float4 wv0 = *(float4*)&sW[(k4 * 4 + 0) * 64 + c4];
            float4 wv1 = *(float4*)&sW[(k4 * 4 + 1) * 64 + c4];
            float4 wv2 = *(float4*)&sW[(k4 * 4 + 2) * 64 + c4];
            float4 wv3 = *(float4*)&sW[(k4 * 4 + 3) * 64 + c4];
#pragma unroll
            for (int r = 0; r < 4; r++) {
                float4 a = *(float4*)&sA[(m + 16 * r) * 64 + k4 * 4];
                acc[r].x += a.x * wv0.x; acc[r].y += a.x * wv0.y; acc[r].z += a.x * wv0.z; acc[r].w += a.x * wv0.w;
                acc[r].x += a.y * wv1.x; acc[r].y += a.y * wv1.y; acc[r].z += a.y * wv1.z; acc[r].w += a.y * wv1.w;
                acc[r].x += a.z * wv2.x; acc[r].y += a.z * wv2.y; acc[r].z += a.z * wv2.z; acc[r].w += a.z * wv2.w;
                acc[r].x += a.w * wv3.x; acc[r].y += a.w * wv3.y; acc[r].z += a.w * wv3.z; acc[r].w += a.w * wv3.w;
            }
        }
#pragma unroll
        for (int r = 0; r < 4; r++) {
            int row = g0 + m + 16 * r;
            float s = SCALE ? g_dinv[row] : 1.f;
            float4 o;
            o.x = fmaxf(acc[r].x, 0.f) * s;
            o.y = fmaxf(acc[r].y, 0.f) * s;
            o.z = fmaxf(acc[r].z, 0.f) * s;
            o.w = fmaxf(acc[r].w, 0.f) * s;
            *(float4*)&dst[row * 64 + c4] = o;
        }
    }
}

// ---------------- LSTM layer-0 input projection: outer-product tiling --------
// Tile = 32 rows x 256 gates; thread computes 8 rows x 4 gates (2 gate-pairs).
#define WGP_STRIDE 65
__global__ void __launch_bounds__(256) k_xproj(const float* __restrict__ Wih,
                                               const float* __restrict__ bih,
                                               const float* __restrict__ bhh) {
    extern __shared__ __align__(16) char smraw[];
    u64t* sWgp  = (u64t*)smraw;                  // 128 * 65 = 8320 u64t
    u64t* sxdup = sWgp + 128 * WGP_STRIDE;       // 32 * 64 = 2048 u64t
    u64t* sBgp  = sxdup + 2048;                  // 128 u64t
    int tid = threadIdx.x;
    int gq = tid & 63;        // gate-quad: gates 4gq..4gq+3
    int rq = tid >> 6;        // row-octet: rows 8rq..8rq+7

    for (int i = tid; i < 128 * 64; i += 256) {
        int gp = i >> 6, j = i & 63;
        sWgp[gp * WGP_STRIDE + j] = pack2(Wih[(2 * gp) * 64 + j], Wih[(2 * gp + 1) * 64 + j]);
    }
    if (tid < 128)
        sBgp[tid] = pack2(bih[2 * tid] + bhh[2 * tid], bih[2 * tid + 1] + bhh[2 * tid + 1]);
    __syncthreads();

    const u64t* wrow0 = &sWgp[(2 * gq) * WGP_STRIDE];       // 16B-aligned rows
    const u64t* wrow1 = &sWgp[(2 * gq + 1) * WGP_STRIDE];   // 8B-aligned only
    u64t bg0 = sBgp[2 * gq], bg1 = sBgp[2 * gq + 1];

#pragma unroll 1
    for (int tile = blockIdx.x; tile < NTILE; tile += gridDim.x) {
        int g0 = tile * 32;
#pragma unroll
        for (int k = 0; k < 2; k++) {
            int i4 = tid + k * 256;           // 512 float4 total
            int r = i4 >> 4, j4 = i4 & 15;
            float4 v = *(const float4*)&g_fB[(g0 + r) * 64 + j4 * 4];
            sxdup[r * 64 + j4 * 4 + 0] = pack2(v.x, v.x);
            sxdup[r * 64 + j4 * 4 + 1] = pack2(v.y, v.y);
            sxdup[r * 64 + j4 * 4 + 2] = pack2(v.z, v.z);
            sxdup[r * 64 + j4 * 4 + 3] = pack2(v.w, v.w);
        }
        __syncthreads();
        u64t acc[8][2];
#pragma unroll
        for (int r = 0; r < 8; r++) { acc[r][0] = bg0; acc[r][1] = bg1; }
#pragma unroll 4
        for (int j2 = 0; j2 < 32; j2++) {
            ulonglong2 w0 = *(const ulonglong2*)&wrow0[j2 * 2];   // aligned
            u64t w1x = wrow1[j2 * 2];                             // LDS.64 pair
            u64t w1y = wrow1[j2 * 2 + 1];
#pragma unroll
            for (int r = 0; r < 8; r++) {
                ulonglong2 xv = *(const ulonglong2*)&sxdup[(8 * rq + r) * 64 + j2 * 2];
                ffma2(acc[r][0], w0.x, xv.x);
                ffma2(acc[r][0], w0.y, xv.y);
                ffma2(acc[r][1], w1x, xv.x);
                ffma2(acc[r][1], w1y, xv.y);
            }
        }
        u64t* outp = (u64t*)g_xp;
#pragma unroll
        for (int r = 0; r < 8; r++) {
            ulonglong2 st;
            st.x = acc[r][0]; st.y = acc[r][1];
            *(ulonglong2*)&outp[(u64t)(g0 + 8 * rq + r) * 128 + 2 * gq] = st;
        }
        __syncthreads();
    }
}

// ---------------- fused 2-layer LSTM + output projection (NB=14/block) ------
__device__ __forceinline__ float sigf(float x) { return 1.f / (1.f + __expf(-x)); }
__device__ __forceinline__ float tanhfast(float x) { return 1.f - 2.f / (__expf(2.f * x) + 1.f); }

__global__ void __launch_bounds__(256, 1) k_lstm(
    const float* __restrict__ Whh0,
    const float* __restrict__ Wih1, const float* __restrict__ Whh1,
    const float* __restrict__ bih1, const float* __restrict__ bhh1,
    const float* __restrict__ Wout, const float* __restrict__ bout,
    float* __restrict__ out)
{
    extern __shared__ float sm[];
    float* sW0  = sm;                  // 16384
    float* sWi1 = sm + 16384;          // 16384
    float* sW1  = sm + 32768;          // 16384
    float* sh0  = sm + 49152;          // NB*64 = 896
    float* sh1  = sh0 + NB * 64;       // 896
    float* sg   = sh1 + NB * 64;       // NB*256 = 3584
    float* sB1  = sg + NB * 256;       // 256

    int tid = threadIdx.x;
    for (int i = tid; i < NG * HID; i += 256) {
        int r = i >> 6, c = i & 63;
        int pos = r * 64 + (((c >> 2) ^ (r & 15)) << 2) + (c & 3);
        sW0[pos]  = Whh0[i];
        sWi1[pos] = Wih1[i];
        sW1[pos]  = Whh1[i];
    }
    sB1[tid] = bih1[tid] + bhh1[tid];
    for (int i = tid; i < NB * 64; i += 256) { sh0[i] = 0.f; sh1[i] = 0.f; }
    int gtype = tid >> 6;   // 0:i 1:f 2:g 3:o
    int wbase = tid * 64;
    int wrot  = tid & 15;
    __syncthreads();
    u64t b1p = pack2(sB1[tid], 0.f);

    int n0 = blockIdx.x * NB;
    float c0[4] = {0.f, 0.f, 0.f, 0.f};
    float c1[4] = {0.f, 0.f, 0.f, 0.f};

#pragma unroll 1
    for (int t = 0; t < WIN; t++) {
        // ---- layer 0 gates ----
        u64t acc[NB];
#pragma unroll
        for (int nn = 0; nn < NB; nn++) {
            int n = n0 + nn;
            int nc = (n < NODES) ? n : (NODES - 1);
            acc[nn] = pack2(g_xp[(t * NODES + nc) * NG + tid], 0.f);
        }
#pragma unroll 8
        for (int j4 = 0; j4 < 16; j4++) {
            ulonglong2 wv = *(const ulonglong2*)&sW0[wbase + ((j4 ^ wrot) << 2)];
#pragma unroll
            for (int nn = 0; nn < NB; nn++) {
                ulonglong2 h = *(const ulonglong2*)&sh0[nn * 64 + j4 * 4];
                ffma2(acc[nn], wv.x, h.x);
                ffma2(acc[nn], wv.y, h.y);
            }
        }
#pragma unroll
        for (int nn = 0; nn < NB; nn++) {
            float v = hsum2(acc[nn]);
            sg[nn * 256 + tid] = (gtype == 2) ? tanhfast(v) : sigf(v);
        }
        __syncthreads();
#pragma unroll
        for (int r = 0; r < 4; r++) {
            int idx = tid + 256 * r;
            if (idx < NB * 64) {
                int nn = idx >> 6, e = idx & 63;
                float gi = sg[nn * 256 + e],       gf = sg[nn * 256 + 64 + e];
                float gg = sg[nn * 256 + 128 + e], go = sg[nn * 256 + 192 + e];
                c0[r] = gf * c0[r] + gi * gg;
                sh0[idx] = go * tanhfast(c0[r]);
            }
        }
        __syncthreads();
        // ---- layer 1 gates ----
#pragma unroll
        for (int nn = 0; nn < NB; nn++) acc[nn] = b1p;
#pragma unroll 8
        for (int j4 = 0; j4 < 16; j4++) {
            int wo = (j4 ^ wrot) << 2;
            ulonglong2 wi = *(const ulonglong2*)&sWi1[wbase + wo];
            ulonglong2 wh = *(const ulonglong2*)&sW1[wbase + wo];
#pragma unroll
            for (int nn = 0; nn < NB; nn++) {
                ulonglong2 h0 = *(const ulonglong2*)&sh0[nn * 64 + j4 * 4];
                ulonglong2 h1 = *(const ulonglong2*)&sh1[nn * 64 + j4 * 4];
                ffma2(acc[nn], wi.x, h0.x);
                ffma2(acc[nn], wi.y, h0.y);
                ffma2(acc[nn], wh.x, h1.x);
                ffma2(acc[nn], wh.y, h1.y);
            }
        }
#pragma unroll
        for (int nn = 0; nn < NB; nn++) {
            float v = hsum2(acc[nn]);
            sg[nn * 256 + tid] = (gtype == 2) ? tanhfast(v) : sigf(v);
        }
        __syncthreads();
#pragma unroll
        for (int r = 0; r < 4; r++) {
            int idx = tid + 256 * r;
            if (idx < NB * 64) {
                int nn = idx >> 6, e = idx & 63;
                float gi = sg[nn * 256 + e],       gf = sg[nn * 256 + 64 + e];
                float gg = sg[nn * 256 + 128 + e], go = sg[nn * 256 + 192 + e];
                c1[r] = gf * c1[r] + gi * gg;
                sh1[idx] = go * tanhfast(c1[r]);
            }
        }
        __syncthreads();
    }
    // ---- output projection: 14 nodes x 96 outputs ----
#pragma unroll 1
    for (int i = tid; i < NB * 96; i += 256) {
        int nn = i / 96, o = i - nn * 96;
        int n = n0 + nn;
        if (n < NODES) {
            float a = bout[o];
#pragma unroll
            for (int k = 0; k < 64; k++)
                a += sh1[nn * 64 + k] * Wout[k * 96 + o];
            out[n * 96 + o] = a;
        }
    }
}

// ---------------- launcher ---------------------------------------------------
extern "C" void kernel_launch(void* const* d_in, const int* in_sizes, int n_in,
                              void* d_out, int out_size) {
    const float* x    = (const float*)d_in[0];
    const int*   ei   = (const int*)  d_in[1];
    const float* W1   = (const float*)d_in[2];
    const float* b1   = (const float*)d_in[3];
    const float* W2   = (const float*)d_in[4];
    const float* b2   = (const float*)d_in[5];
    const float* W3   = (const float*)d_in[6];
    const float* b3   = (const float*)d_in[7];
    const float* W4   = (const float*)d_in[8];
    const float* b4   = (const float*)d_in[9];
    const float* Wih0 = (const float*)d_in[10];
    const float* Whh0 = (const float*)d_in[11];
    const float* bih0 = (const float*)d_in[12];
    const float* bhh0 = (const float*)d_in[13];
    const float* Wih1 = (const float*)d_in[14];
    const float* Whh1 = (const float*)d_in[15];
    const float* bih1 = (const float*)d_in[16];
    const float* bhh1 = (const float*)d_in[17];
    const float* Wout = (const float*)d_in[18];
    const float* bout = (const float*)d_in[19];
    float* out = (float*)d_out;

    const int XP_SMEM   = (128 * WGP_STRIDE + 2048 + 128) * 8;                // 83968
    const int LSTM_SMEM = (3 * 16384 + NB * 64 * 2 + NB * 256 + 256) * 4;     // 219136
    cudaFuncSetAttribute(k_xproj, cudaFuncAttributeMaxDynamicSharedMemorySize, XP_SMEM);
    cudaFuncSetAttribute(k_lstm,  cudaFuncAttributeMaxDynamicSharedMemorySize, LSTM_SMEM);

    // graph preprocessing (separate launches; g_deg zeroed by last GCN layer)
    k_count<<<3000, 256>>>(ei);
    k_scanA<<<188, 256>>>();
    k_scanC<<<188, 256>>>(x);
    k_fill<<<3000, 256>>>(ei);

    // GCN stack (fused aggregate + GEMM, double-buffered A/B)
    k_layer1<<<750, 256>>>(W1, b1);                  // xs -> A
    k_layer64<true,  true ><<<NGRP64, 256>>>(W2, b2);   // A -> B
    k_layer64<false, true ><<<NGRP64, 256>>>(W3, b3);   // B -> A
    k_layer64<true,  false><<<NGRP64, 256>>>(W4, b4);   // A -> B (unscaled; zeroes g_deg)

    // LSTM
    k_xproj<<<750, 256, XP_SMEM>>>(Wih0, bih0, bhh0);
    k_lstm<<<NBLK, 256, LSTM_SMEM>>>(Whh0, Wih1, Whh1, bih1, bhh1, Wout, bout, out);
}

// round 14
// speedup vs baseline: 1.0811x; 1.0804x over previous
#include <cuda_runtime.h>

#define NN 48000          // NUM_NODES * WINDOW
#define NODES 2000
#define WIN 24
#define EE 768000
#define EEPAD (EE + NN * 8)   // CSR capacity with per-row pad to multiple of 8
#define FIN 12
#define HID 64
#define NG 256            // 4 * LSTM_H gates
#define NB 14             // nodes per block in fused LSTM (143 blocks x 14 = 2002)
#define NBLK 143
#define NGRP1 3000        // NN / 16  (layer1 groups)
#define NGRP64 1500       // NN / 32  (layer64 groups)
#define NTILE 1500        // NN / 32  (xproj tiles, 32 rows each)
#define SIDX_CAP 3072     // layer64 smem index staging capacity (ints)

typedef unsigned long long u64t;

// ---------------- packed f32x2 helpers (Blackwell) ---------------------------
__device__ __forceinline__ void ffma2(u64t &d, u64t a, u64t b) {
    asm("fma.rn.f32x2 %0, %1, %2, %0;" : "+l"(d) : "l"(a), "l"(b));
}
__device__ __forceinline__ u64t add2(u64t a, u64t b) {
    u64t r; asm("add.rn.f32x2 %0, %1, %2;" : "=l"(r) : "l"(a), "l"(b)); return r;
}
__device__ __forceinline__ u64t pack2(float lo, float hi) {
    u64t r; asm("mov.b64 %0, {%1, %2};" : "=l"(r) : "f"(lo), "f"(hi)); return r;
}
__device__ __forceinline__ float hsum2(u64t v) {
    float lo, hi; asm("mov.b64 {%0, %1}, %2;" : "=f"(lo), "=f"(hi) : "l"(v));
    return lo + hi;
}
__device__ __forceinline__ float2 unpack2(u64t v) {
    float lo, hi; asm("mov.b64 {%0, %1}, %2;" : "=f"(lo), "=f"(hi) : "l"(v));
    return make_float2(lo, hi);
}

// ---------------- scratch (device globals) -----------------------------------
// Row NN of g_xs / g_fA / g_fB is a sentinel row: NEVER written, stays zero
// (device globals are zero-initialized). CSR rows are padded to multiples of 8
// with index NN, so gathers have no tails and no bounds checks.
__device__ int   g_deg[NN];        // invariant: zero at kernel_launch entry
__device__ int   g_offs[NN];       // inclusive scan of PADDED degrees
__device__ int   g_cursor[NN];
__device__ float g_dinv[NN];
__device__ __align__(16) int g_csrc[EEPAD];
__device__ __align__(16) float g_xs[(NN + 1) * FIN];
__device__ __align__(16) float g_fA[(NN + 1) * HID];
__device__ __align__(16) float g_fB[(NN + 1) * HID];
__device__ __align__(16) float g_xp[NN * NG];
__device__ int g_bsum[256];

// ---------------- graph preprocessing (separate launches) --------------------
__global__ void k_count(const int* __restrict__ ei) {
    int e = blockIdx.x * 256 + threadIdx.x;
    if (e < EE) atomicAdd(&g_deg[ei[EE + e]], 1);
}
// per-chunk inclusive scan of PADDED degrees; chunk totals to g_bsum
__global__ void k_scanA() {
    __shared__ int s[256];
    int tid = threadIdx.x;
    int i = blockIdx.x * 256 + tid;
    int pd = 0;
    if (i < NN) pd = (g_deg[i] + 7) & ~7;
    s[tid] = pd;
    __syncthreads();
    for (int o = 1; o < 256; o <<= 1) {
        int t = (tid >= o) ? s[tid - o] : 0;
        __syncthreads();
        s[tid] += t;
        __syncthreads();
    }
    if (i < NN) g_offs[i] = s[tid];
    if (tid == 255) g_bsum[blockIdx.x] = s[255];
}
// chunk base (local reduction of g_bsum) + offs/cursor/sentinels/dinv/xs
__global__ void k_scanC(const float* __restrict__ x) {
    __shared__ int s[256];
    int b = blockIdx.x, tid = threadIdx.x;
    int v = (tid < b) ? g_bsum[tid] : 0;   // b <= 187 < 256
    s[tid] = v;
    __syncthreads();
    for (int o = 128; o > 0; o >>= 1) {
        if (tid < o) s[tid] += s[tid + o];
        __syncthreads();
    }
    int base = s[0];
    int i = b * 256 + tid;
    if (i < NN) {
        int dg = g_deg[i];
        int pd = (dg + 7) & ~7;
        int off = g_offs[i] + base;       // end of this row (padded)
        int start = off - pd;
        g_offs[i] = off;
        g_cursor[i] = start;
        for (int k = dg; k < pd; k++) g_csrc[start + k] = NN;   // sentinels
        float di = rsqrtf((float)dg + 1.0f);
        g_dinv[i] = di;
#pragma unroll
        for (int f = 0; f < FIN; f++) g_xs[i * FIN + f] = x[i * FIN + f] * di;
    }
}
__global__ void k_fill(const int* __restrict__ ei) {
    int e = blockIdx.x * 256 + threadIdx.x;
    if (e < EE) {
        int sn = ei[e];
        int d = ei[EE + e];
        int p = atomicAdd(&g_cursor[d], 1);
        g_csrc[p] = sn;
    }
}

// ---------------- layer 1: fused 12-wide aggregate + 12->64 GEMM -------------
__global__ void __launch_bounds__(256) k_layer1(const float* __restrict__ W1,
                                                const float* __restrict__ b1) {
    __shared__ float sW[FIN * 64];
    __shared__ float sb[64];
    __shared__ float sU[16 * FIN];
    int tid = threadIdx.x;
    int w = tid >> 5, lane = tid & 31;
    int sub = lane >> 4, f = lane & 15;
    for (int i = tid; i < FIN * 64; i += 256) sW[i] = W1[i];
    if (tid < 64) sb[tid] = b1[tid];
    __syncthreads();

#pragma unroll 1
    for (int grp = blockIdx.x; grp < NGRP1; grp += gridDim.x) {
        int g0 = grp * 16;
        {
            int m = w * 2 + sub;
            int d = g0 + m;
            if (f < FIN) {
                int dg = g_deg[d];
                int pd = (dg + 7) & ~7;
                int end = g_offs[d];
                float acc = 0.f;
#pragma unroll 1
                for (int e = end - pd; e < end; e += 4) {
                    int4 iv = *(const int4*)&g_csrc[e];
                    acc += g_xs[iv.x * FIN + f] + g_xs[iv.y * FIN + f]
                         + g_xs[iv.z * FIN + f] + g_xs[iv.w * FIN + f];
                }
                acc += g_xs[d * FIN + f];
                sU[m * FIN + f] = g_dinv[d] * acc;
            }
        }
        __syncthreads();
        {
            int c4 = (tid & 15) * 4;
            int m = tid >> 4;
            float4 acc = make_float4(sb[c4], sb[c4 + 1], sb[c4 + 2], sb[c4 + 3]);
#pragma unroll
            for (int k = 0; k < FIN; k++) {
                float a = sU[m * FIN + k];
                float4 wv = *(float4*)&sW[k * 64 + c4];
                acc.x += a * wv.x; acc.y += a * wv.y; acc.z += a * wv.z; acc.w += a * wv.w;
            }
            float s = g_dinv[g0 + m];
            float4 r;
            r.x = fmaxf(acc.x, 0.f) * s;
            r.y = fmaxf(acc.y, 0.f) * s;
            r.z = fmaxf(acc.z, 0.f) * s;
            r.w = fmaxf(acc.w, 0.f) * s;
            *(float4*)&g_fA[(g0 + m) * 64 + c4] = r;
        }
        __syncthreads();
    }
}

// ---------------- fused 64-wide aggregate + 64x64 GEMM (32 dsts/grp) ---------
// Group's CSR indices staged in smem; gather index fetch is LDS, feature
// gathers have 32 loads in flight per warp.
// SRCA: read g_fA else g_fB (write the other). SCALE: scale output by dinv.
// SCALE=false (last layer) also zeroes g_deg per group after its final read.
template <bool SRCA, bool SCALE>
__global__ void __launch_bounds__(256) k_layer64(const float* __restrict__ W,
                                                 const float* __restrict__ b) {
    __shared__ float sW[4096];
    __shared__ float sb[64];
    __shared__ __align__(16) float sA[2048];
    __shared__ __align__(16) int sidx[SIDX_CAP];
    const float* __restrict__ src = SRCA ? g_fA : g_fB;
    float* __restrict__ dst = SRCA ? g_fB : g_fA;
    int tid = threadIdx.x;
    int w = tid >> 5, lane = tid & 31;
    for (int i = tid; i < 4096; i += 256) sW[i] = W[i];
    if (tid < 64) sb[tid] = b[tid];
    __syncthreads();

#pragma unroll 1
    for (int grp = blockIdx.x; grp < NGRP64; grp += gridDim.x) {
        int g0 = grp * 32;
        // stage indices: [start0, endL) is the contiguous padded CSR range
        int start0 = g_offs[g0] - ((g_deg[g0] + 7) & ~7);
        int endL = g_offs[g0 + 31];
        int L = endL - start0;                 // multiple of 8, 32B-aligned base
        bool use_s = (L <= SIDX_CAP);          // uniform across block
        if (use_s) {
#pragma unroll 1
            for (int i = tid * 4; i < L; i += 1024)
                *(int4*)&sidx[i] = *(const int4*)&g_csrc[start0 + i];
        }
        __syncthreads();
        const int* ip = use_s ? (const int*)sidx - start0 : (const int*)g_csrc;
        // gather: warp handles 4 dsts, 8 edges per dst per round
        {
            int d[4]; int e[4], en[4]; u64t acc[4];
#pragma unroll
            for (int p = 0; p < 4; p++) {
                d[p] = g0 + w + p * 8;
                en[p] = g_offs[d[p]];
                int pd = (g_deg[d[p]] + 7) & ~7;
                e[p] = en[p] - pd;
                acc[p] = 0ULL;
            }
#pragma unroll 1
            for (;;) {
                bool any = false;
#pragma unroll
                for (int p = 0; p < 4; p++) {
                    if (e[p] < en[p]) {
                        any = true;
                        int4 i0 = *(const int4*)&ip[e[p]];
                        int4 i1 = *(const int4*)&ip[e[p] + 4];
                        u64t v0 = *(const u64t*)&src[i0.x * 64 + lane * 2];
                        u64t v1 = *(const u64t*)&src[i0.y * 64 + lane * 2];
                        u64t v2 = *(const u64t*)&src[i0.z * 64 + lane * 2];
                        u64t v3 = *(const u64t*)&src[i0.w * 64 + lane * 2];
                        u64t v4 = *(const u64t*)&src[i1.x * 64 + lane * 2];
                        u64t v5 = *(const u64t*)&src[i1.y * 64 + lane * 2];
                        u64t v6 = *(const u64t*)&src[i1.z * 64 + lane * 2];
                        u64t v7 = *(const u64t*)&src[i1.w * 64 + lane * 2];
                        acc[p] = add2(acc[p],
                                 add2(add2(add2(v0, v1), add2(v2, v3)),
                                      add2(add2(v4, v5), add2(v6, v7))));
                        e[p] += 8;
                    }
                }
                if (!any) break;
            }
#pragma unroll
            for (int p = 0; p < 4; p++) {
                acc[p] = add2(acc[p], *(const u64t*)&src[d[p] * 64 + lane * 2]);
                float2 r = unpack2(acc[p]);
                float di = g_dinv[d[p]];
                sA[(w + p * 8) * 64 + lane * 2]     = di * r.x;
                sA[(w + p * 8) * 64 + lane * 2 + 1] = di * r.y;
            }
        }
        __syncthreads();
        if (!SCALE) {                     // last layer: restore deg==0 invariant
            if (tid < 32) g_deg[g0 + tid] = 0;
        }
        // GEMM 32x64 @ 64x64 + bias + relu (+dinv) — 8 outputs/thread
        {
            int c4 = (tid & 15) * 4;
            int m = tid >> 4;                  // rows m and m+16
            float4 acc0 = make_float4(sb[c4], sb[c4 + 1], sb[c4 + 2], sb[c4 + 3]);
            float4 acc1 = acc0;
#pragma unroll
            for (int k4 = 0; k4 < 16; k4++) {
                float4 a0 = *(float4*)&sA[m * 64 + k4 * 4];
                float4 a1 = *(float4*)&sA[(m + 16) * 64 + k4 * 4];
                float4 wv;
                wv = *(float4*)&sW[(k4 * 4 + 0) * 64 + c4];
                acc0.x += a0.x * wv.x; acc0.y += a0.x * wv.y; acc0.z += a0.x * wv.z; acc0.w += a0.x * wv.w;
                acc1.x += a1.x * wv.x; acc1.y += a1.x * wv.y; acc1.z += a1.x * wv.z; acc1.w += a1.x * wv.w;
                wv = *(float4*)&sW[(k4 * 4 + 1) * 64 + c4];
                acc0.x += a0.y * wv.x; acc0.y += a0.y * wv.y; acc0.z += a0.y * wv.z; acc0.w += a0.y * wv.w;
                acc1.x += a1.y * wv.x; acc1.y += a1.y * wv.y; acc1.z += a1.y * wv.z; acc1.w += a1.y * wv.w;
                wv = *(float4*)&sW[(k4 * 4 + 2) * 64 + c4];
                acc0.x += a0.z * wv.x; acc0.y += a0.z * wv.y; acc0.z += a0.z * wv.z; acc0.w += a0.z * wv.w;
                acc1.x += a1.z * wv.x; acc1.y += a1.z * wv.y; acc1.z += a1.z * wv.z; acc1.w += a1.z * wv.w;
                wv = *(float4*)&sW[(k4 * 4 + 3) * 64 + c4];
                acc0.x += a0.w * wv.x; acc0.y += a0.w * wv.y; acc0.z += a0.w * wv.z; acc0.w += a0.w * wv.w;
                acc1.x += a1.w * wv.x; acc1.y += a1.w * wv.y; acc1.z += a1.w * wv.z; acc1.w += a1.w * wv.w;
            }
            float s0 = SCALE ? g_dinv[g0 + m] : 1.f;
            float s1 = SCALE ? g_dinv[g0 + m + 16] : 1.f;
            float4 r0, r1;
            r0.x = fmaxf(acc0.x, 0.f) * s0; r0.y = fmaxf(acc0.y, 0.f) * s0;
            r0.z = fmaxf(acc0.z, 0.f) * s0; r0.w = fmaxf(acc0.w, 0.f) * s0;
            r1.x = fmaxf(acc1.x, 0.f) * s1; r1.y = fmaxf(acc1.y, 0.f) * s1;
            r1.z = fmaxf(acc1.z, 0.f) * s1; r1.w = fmaxf(acc1.w, 0.f) * s1;
            *(float4*)&dst[(g0 + m) * 64 + c4] = r0;
            *(float4*)&dst[(g0 + m + 16) * 64 + c4] = r1;
        }
        __syncthreads();
    }
}

// ---------------- LSTM layer-0 input projection: outer-product tiling --------
// Tile = 32 rows x 256 gates; thread computes 8 rows x 4 gates (2 gate-pairs).
#define WGP_STRIDE 65
__global__ void __launch_bounds__(256) k_xproj(const float* __restrict__ Wih,
                                               const float* __restrict__ bih,
                                               const float* __restrict__ bhh) {
    extern __shared__ __align__(16) char smraw[];
    u64t* sWgp  = (u64t*)smraw;                  // 128 * 65 = 8320 u64t
    u64t* sxdup = sWgp + 128 * WGP_STRIDE;       // 32 * 64 = 2048 u64t
    u64t* sBgp  = sxdup + 2048;                  // 128 u64t
    int tid = threadIdx.x;
    int gq = tid & 63;        // gate-quad: gates 4gq..4gq+3
    int rq = tid >> 6;        // row-octet: rows 8rq..8rq+7

    for (int i = tid; i < 128 * 64; i += 256) {
        int gp = i >> 6, j = i & 63;
        sWgp[gp * WGP_STRIDE + j] = pack2(Wih[(2 * gp) * 64 + j], Wih[(2 * gp + 1) * 64 + j]);
    }
    if (tid < 128)
        sBgp[tid] = pack2(bih[2 * tid] + bhh[2 * tid], bih[2 * tid + 1] + bhh[2 * tid + 1]);
    __syncthreads();

    const u64t* wrow0 = &sWgp[(2 * gq) * WGP_STRIDE];       // 16B-aligned rows
    const u64t* wrow1 = &sWgp[(2 * gq + 1) * WGP_STRIDE];   // 8B-aligned only
    u64t bg0 = sBgp[2 * gq], bg1 = sBgp[2 * gq + 1];

#pragma unroll 1
    for (int tile = blockIdx.x; tile < NTILE; tile += gridDim.x) {
        int g0 = tile * 32;
#pragma unroll
        for (int k = 0; k < 2; k++) {
            int i4 = tid + k * 256;           // 512 float4 total
            int r = i4 >> 4, j4 = i4 & 15;
            float4 v = *(const float4*)&g_fB[(g0 + r) * 64 + j4 * 4];
            sxdup[r * 64 + j4 * 4 + 0] = pack2(v.x, v.x);
            sxdup[r * 64 + j4 * 4 + 1] = pack2(v.y, v.y);
            sxdup[r * 64 + j4 * 4 + 2] = pack2(v.z, v.z);
            sxdup[r * 64 + j4 * 4 + 3] = pack2(v.w, v.w);
        }
        __syncthreads();
        u64t acc[8][2];
#pragma unroll
        for (int r = 0; r < 8; r++) { acc[r][0] = bg0; acc[r][1] = bg1; }
#pragma unroll 4
        for (int j2 = 0; j2 < 32; j2++) {
            ulonglong2 w0 = *(const ulonglong2*)&wrow0[j2 * 2];   // aligned
            u64t w1x = wrow1[j2 * 2];                             // LDS.64 pair
            u64t w1y = wrow1[j2 * 2 + 1];
#pragma unroll
            for (int r = 0; r < 8; r++) {
                ulonglong2 xv = *(const ulonglong2*)&sxdup[(8 * rq + r) * 64 + j2 * 2];
                ffma2(acc[r][0], w0.x, xv.x);
                ffma2(acc[r][0], w0.y, xv.y);
                ffma2(acc[r][1], w1x, xv.x);
                ffma2(acc[r][1], w1y, xv.y);
            }
        }
        u64t* outp = (u64t*)g_xp;
#pragma unroll
        for (int r = 0; r < 8; r++) {
            ulonglong2 st;
            st.x = acc[r][0]; st.y = acc[r][1];
            *(ulonglong2*)&outp[(u64t)(g0 + 8 * rq + r) * 128 + 2 * gq] = st;
        }
        __syncthreads();
    }
}

// ---------------- fused 2-layer LSTM + output projection ---------------------
// Node-split layout: threads 0-127 own local nodes 0-6, threads 128-255 own
// nodes 7-13. Each thread computes TWO gates: ht and ht+128 (ht = tid & 127).
// Gate ht is i (ht<64) or f (sigmoid either way); gate ht+128 is g (tanh,
// ht<64) or o (sigmoid). Layer-0 weight rows live in registers (no LDS);
// layer-1 weights stay in XOR-swizzled smem (row-step 1 -> conflict-free).
// This halves the per-warp h-broadcast redundancy (the crossbar bottleneck).
__device__ __forceinline__ float sigf(float x) { return 1.f / (1.f + __expf(-x)); }
__device__ __forceinline__ float tanhfast(float x) { return 1.f - 2.f / (__expf(2.f * x) + 1.f); }

__global__ void __launch_bounds__(256, 1) k_lstm(
    const float* __restrict__ Whh0,
    const float* __restrict__ Wih1, const float* __restrict__ Whh1,
    const float* __restrict__ bih1, const float* __restrict__ bhh1,
    const float* __restrict__ Wout, const float* __restrict__ bout,
    float* __restrict__ out)
{
    extern __shared__ float sm[];
    float* sWi1 = sm;                  // 16384 (swizzled)
    float* sW1  = sm + 16384;          // 16384 (swizzled)
    float* sh0  = sm + 32768;          // NB*64 = 896
    float* sh1  = sh0 + NB * 64;       // 896
    float* sg   = sh1 + NB * 64;       // NB*256 = 3584

    int tid = threadIdx.x;
    int ht   = tid & 127;              // gate-half index: gates ht and ht+128
    int half = tid >> 7;               // node half: 0 -> nodes 0-6, 1 -> 7-13
    for (int i = tid; i < NG * HID; i += 256) {
        int r = i >> 6, c = i & 63;
        int pos = r * 64 + (((c >> 2) ^ (r & 15)) << 2) + (c & 3);
        sWi1[pos] = Wih1[i];
        sW1[pos]  = Whh1[i];
    }
    for (int i = tid; i < NB * 64; i += 256) { sh0[i] = 0.f; sh1[i] = 0.f; }
    // layer-0 weight rows ht and ht+128 -> registers
    ulonglong2 wA[16], wB[16];
#pragma unroll
    for (int j4 = 0; j4 < 16; j4++) {
        wA[j4] = *(const ulonglong2*)&Whh0[ht * 64 + j4 * 4];
        wB[j4] = *(const ulonglong2*)&Whh0[(ht + 128) * 64 + j4 * 4];
    }
    u64t bA = pack2(bih1[ht] + bhh1[ht], 0.f);
    u64t bB = pack2(bih1[ht + 128] + bhh1[ht + 128], 0.f);
    bool gB_tanh = (ht < 64);          // gate ht+128 is 'g' (tanh) iff ht<64
    int wbaseA = ht * 64;
    int wbaseB = (ht + 128) * 64;
    int wrot = ht & 15;                // same rot for ht+128
    int nbase = half * 7;              // local node offset
    __syncthreads();

    int n0 = blockIdx.x * NB;
    float c0[4] = {0.f, 0.f, 0.f, 0.f};
    float c1[4] = {0.f, 0.f, 0.f, 0.f};

#pragma unroll 1
    for (int t = 0; t < WIN; t++) {
        // ---- layer 0 gates (7 nodes, 2 gates per thread) ----
        u64t accA[7], accB[7];
#pragma unroll
        for (int nn = 0; nn < 7; nn++) {
            int n = n0 + nbase + nn;
            int nc = (n < NODES) ? n : (NODES - 1);
            const float* xp = &g_xp[(u64t)(t * NODES + nc) * NG];
            accA[nn] = pack2(xp[ht], 0.f);
            accB[nn] = pack2(xp[ht + 128], 0.f);
        }
#pragma unroll 8
        for (int j4 = 0; j4 < 16; j4++) {
#pragma unroll
            for (int nn = 0; nn < 7; nn++) {
                ulonglong2 h = *(const ulonglong2*)&sh0[(nbase + nn) * 64 + j4 * 4];
                ffma2(accA[nn], wA[j4].x, h.x);
                ffma2(accA[nn], wA[j4].y, h.y);
                ffma2(accB[nn], wB[j4].x, h.x);
                ffma2(accB[nn], wB[j4].y, h.y);
            }
        }
#pragma unroll
        for (int nn = 0; nn < 7; nn++) {
            float vA = hsum2(accA[nn]);
            float vB = hsum2(accB[nn]);
            int g = (nbase + nn) * 256;
            sg[g + ht] = sigf(vA);                            // i or f
            sg[g + 128 + ht] = gB_tanh ? tanhfast(vB) : sigf(vB);  // g or o
        }
        __syncthreads();
#pragma unroll
        for (int r = 0; r < 4; r++) {
            int idx = tid + 256 * r;
            if (idx < NB * 64) {
                int nn = idx >> 6, e = idx & 63;
                float gi = sg[nn * 256 + e],       gf = sg[nn * 256 + 64 + e];
                float gg = sg[nn * 256 + 128 + e], go = sg[nn * 256 + 192 + e];
                c0[r] = gf * c0[r] + gi * gg;
                sh0[idx] = go * tanhfast(c0[r]);
            }
        }
        __syncthreads();
        // ---- layer 1 gates ----
#pragma unroll
        for (int nn = 0; nn < 7; nn++) { accA[nn] = bA; accB[nn] = bB; }
#pragma unroll 8
        for (int j4 = 0; j4 < 16; j4++) {
            int wo = (j4 ^ wrot) << 2;
            ulonglong2 wiA = *(const ulonglong2*)&sWi1[wbaseA + wo];
            ulonglong2 wiB = *(const ulonglong2*)&sWi1[wbaseB + wo];
            ulonglong2 whA = *(const ulonglong2*)&sW1[wbaseA + wo];
            ulonglong2 whB = *(const ulonglong2*)&sW1[wbaseB + wo];
#pragma unroll
            for (int nn = 0; nn < 7; nn++) {
                ulonglong2 h0 = *(const ulonglong2*)&sh0[(nbase + nn) * 64 + j4 * 4];
                ulonglong2 h1 = *(const ulonglong2*)&sh1[(nbase + nn) * 64 + j4 * 4];
                ffma2(accA[nn], wiA.x, h0.x);
                ffma2(accA[nn], wiA.y, h0.y);
                ffma2(accA[nn], whA.x, h1.x);
                ffma2(accA[nn], whA.y, h1.y);
                ffma2(accB[nn], wiB.x, h0.x);
                ffma2(accB[nn], wiB.y, h0.y);
                ffma2(accB[nn], whB.x, h1.x);
                ffma2(accB[nn], whB.y, h1.y);
            }
        }
#pragma unroll
        for (int nn = 0; nn < 7; nn++) {
            float vA = hsum2(accA[nn]);
            float vB = hsum2(accB[nn]);
            int g = (nbase + nn) * 256;
            sg[g + ht] = sigf(vA);
            sg[g + 128 + ht] = gB_tanh ? tanhfast(vB) : sigf(vB);
        }
        __syncthreads();
#pragma unroll
        for (int r = 0; r < 4; r++) {
            int idx = tid + 256 * r;
            if (idx < NB * 64) {
                int nn = idx >> 6, e = idx & 63;
                float gi = sg[nn * 256 + e],       gf = sg[nn * 256 + 64 + e];
                float gg = sg[nn * 256 + 128 + e], go = sg[nn * 256 + 192 + e];
                c1[r] = gf * c1[r] + gi * gg;
                sh1[idx] = go * tanhfast(c1[r]);
            }
        }
        __syncthreads();
    }
    // ---- output projection: 14 nodes x 96 outputs ----
#pragma unroll 1
    for (int i = tid; i < NB * 96; i += 256) {
        int nn = i / 96, o = i - nn * 96;
        int n = n0 + nn;
        if (n < NODES) {
            float a = bout[o];
#pragma unroll
            for (int k = 0; k < 64; k++)
                a += sh1[nn * 64 + k] * Wout[k * 96 + o];
            out[n * 96 + o] = a;
        }
    }
}

// ---------------- launcher ---------------------------------------------------
extern "C" void kernel_launch(void* const* d_in, const int* in_sizes, int n_in,
                              void* d_out, int out_size) {
    const float* x    = (const float*)d_in[0];
    const int*   ei   = (const int*)  d_in[1];
    const float* W1   = (const float*)d_in[2];
    const float* b1   = (const float*)d_in[3];
    const float* W2   = (const float*)d_in[4];
    const float* b2   = (const float*)d_in[5];
    const float* W3   = (const float*)d_in[6];
    const float* b3   = (const float*)d_in[7];
    const float* W4   = (const float*)d_in[8];
    const float* b4   = (const float*)d_in[9];
    const float* Wih0 = (const float*)d_in[10];
    const float* Whh0 = (const float*)d_in[11];
    const float* bih0 = (const float*)d_in[12];
    const float* bhh0 = (const float*)d_in[13];
    const float* Wih1 = (const float*)d_in[14];
    const float* Whh1 = (const float*)d_in[15];
    const float* bih1 = (const float*)d_in[16];
    const float* bhh1 = (const float*)d_in[17];
    const float* Wout = (const float*)d_in[18];
    const float* bout = (const float*)d_in[19];
    float* out = (float*)d_out;

    const int XP_SMEM   = (128 * WGP_STRIDE + 2048 + 128) * 8;                // 83968
    const int LSTM_SMEM = (2 * 16384 + NB * 64 * 2 + NB * 256) * 4;           // 152576
    cudaFuncSetAttribute(k_xproj, cudaFuncAttributeMaxDynamicSharedMemorySize, XP_SMEM);
    cudaFuncSetAttribute(k_lstm,  cudaFuncAttributeMaxDynamicSharedMemorySize, LSTM_SMEM);

    // graph preprocessing (separate launches; g_deg zeroed by last GCN layer)
    k_count<<<3000, 256>>>(ei);
    k_scanA<<<188, 256>>>();
    k_scanC<<<188, 256>>>(x);
    k_fill<<<3000, 256>>>(ei);

    // GCN stack (fused aggregate + GEMM, double-buffered A/B)
    k_layer1<<<750, 256>>>(W1, b1);                  // xs -> A
    k_layer64<true,  true ><<<750, 256>>>(W2, b2);   // A -> B
    k_layer64<false, true ><<<750, 256>>>(W3, b3);   // B -> A
    k_layer64<true,  false><<<750, 256>>>(W4, b4);   // A -> B (unscaled; zeroes g_deg)

    // LSTM
    k_xproj<<<750, 256, XP_SMEM>>>(Wih0, bih0, bhh0);
    k_lstm<<<NBLK, 256, LSTM_SMEM>>>(Whh0, Wih1, Whh1, bih1, bhh1, Wout, bout, out);
}

// round 15
// speedup vs baseline: 1.0946x; 1.0125x over previous
#include <cuda_runtime.h>

#define NN 48000          // NUM_NODES * WINDOW
#define NODES 2000
#define WIN 24
#define EE 768000
#define EEPAD (EE + NN * 8)   // CSR capacity with per-row pad to multiple of 8
#define FIN 12
#define HID 64
#define NG 256            // 4 * LSTM_H gates
#define NB 14             // nodes per block in fused LSTM (143 blocks x 14 = 2002)
#define NBLK 143
#define NGRP1 3000        // NN / 16  (layer1 groups)
#define NGRP64 1500       // NN / 32  (layer64 groups)
#define NTILE 1500        // NN / 32  (xproj tiles, 32 rows each)
#define SIDX_CAP 3072     // layer64 smem index staging capacity (ints)
#define GRID_L64 592      // 4 blocks/SM x 148 — one perfectly balanced wave
#define GRID_L1  592
#define GRID_XP  296      // 2 blocks/SM x 148 (84KB smem -> 2/SM ceiling)

typedef unsigned long long u64t;

// ---------------- packed f32x2 helpers (Blackwell) ---------------------------
__device__ __forceinline__ void ffma2(u64t &d, u64t a, u64t b) {
    asm("fma.rn.f32x2 %0, %1, %2, %0;" : "+l"(d) : "l"(a), "l"(b));
}
__device__ __forceinline__ u64t add2(u64t a, u64t b) {
    u64t r; asm("add.rn.f32x2 %0, %1, %2;" : "=l"(r) : "l"(a), "l"(b)); return r;
}
__device__ __forceinline__ u64t pack2(float lo, float hi) {
    u64t r; asm("mov.b64 %0, {%1, %2};" : "=l"(r) : "f"(lo), "f"(hi)); return r;
}
__device__ __forceinline__ float hsum2(u64t v) {
    float lo, hi; asm("mov.b64 {%0, %1}, %2;" : "=f"(lo), "=f"(hi) : "l"(v));
    return lo + hi;
}
__device__ __forceinline__ float2 unpack2(u64t v) {
    float lo, hi; asm("mov.b64 {%0, %1}, %2;" : "=f"(lo), "=f"(hi) : "l"(v));
    return make_float2(lo, hi);
}

// ---------------- scratch (device globals) -----------------------------------
// Row NN of g_xs / g_fA / g_fB is a sentinel row: NEVER written, stays zero
// (device globals are zero-initialized). CSR rows are padded to multiples of 8
// with index NN, so gathers have no tails and no bounds checks.
__device__ int   g_deg[NN];        // invariant: zero at kernel_launch entry
__device__ int   g_offs[NN];       // inclusive scan of PADDED degrees
__device__ int   g_cursor[NN];
__device__ float g_dinv[NN];
__device__ __align__(16) int g_csrc[EEPAD];
__device__ __align__(16) float g_xs[(NN + 1) * FIN];
__device__ __align__(16) float g_fA[(NN + 1) * HID];
__device__ __align__(16) float g_fB[(NN + 1) * HID];
__device__ __align__(16) float g_xp[NN * NG];
__device__ int g_bsum[256];

// ---------------- graph preprocessing (separate launches) --------------------
__global__ void k_count(const int* __restrict__ ei) {
    int e = blockIdx.x * 256 + threadIdx.x;
    if (e < EE) atomicAdd(&g_deg[ei[EE + e]], 1);
}
// per-chunk inclusive scan of PADDED degrees; chunk totals to g_bsum
__global__ void k_scanA() {
    __shared__ int s[256];
    int tid = threadIdx.x;
    int i = blockIdx.x * 256 + tid;
    int pd = 0;
    if (i < NN) pd = (g_deg[i] + 7) & ~7;
    s[tid] = pd;
    __syncthreads();
    for (int o = 1; o < 256; o <<= 1) {
        int t = (tid >= o) ? s[tid - o] : 0;
        __syncthreads();
        s[tid] += t;
        __syncthreads();
    }
    if (i < NN) g_offs[i] = s[tid];
    if (tid == 255) g_bsum[blockIdx.x] = s[255];
}
// chunk base (local reduction of g_bsum) + offs/cursor/sentinels/dinv/xs
__global__ void k_scanC(const float* __restrict__ x) {
    __shared__ int s[256];
    int b = blockIdx.x, tid = threadIdx.x;
    int v = (tid < b) ? g_bsum[tid] : 0;   // b <= 187 < 256
    s[tid] = v;
    __syncthreads();
    for (int o = 128; o > 0; o >>= 1) {
        if (tid < o) s[tid] += s[tid + o];
        __syncthreads();
    }
    int base = s[0];
    int i = b * 256 + tid;
    if (i < NN) {
        int dg = g_deg[i];
        int pd = (dg + 7) & ~7;
        int off = g_offs[i] + base;       // end of this row (padded)
        int start = off - pd;
        g_offs[i] = off;
        g_cursor[i] = start;
        for (int k = dg; k < pd; k++) g_csrc[start + k] = NN;   // sentinels
        float di = rsqrtf((float)dg + 1.0f);
        g_dinv[i] = di;
#pragma unroll
        for (int f = 0; f < FIN; f++) g_xs[i * FIN + f] = x[i * FIN + f] * di;
    }
}
__global__ void k_fill(const int* __restrict__ ei) {
    int e = blockIdx.x * 256 + threadIdx.x;
    if (e < EE) {
        int sn = ei[e];
        int d = ei[EE + e];
        int p = atomicAdd(&g_cursor[d], 1);
        g_csrc[p] = sn;
    }
}

// ---------------- layer 1: fused 12-wide aggregate + 12->64 GEMM -------------
__global__ void __launch_bounds__(256) k_layer1(const float* __restrict__ W1,
                                                const float* __restrict__ b1) {
    __shared__ float sW[FIN * 64];
    __shared__ float sb[64];
    __shared__ float sU[16 * FIN];
    int tid = threadIdx.x;
    int w = tid >> 5, lane = tid & 31;
    int sub = lane >> 4, f = lane & 15;
    for (int i = tid; i < FIN * 64; i += 256) sW[i] = W1[i];
    if (tid < 64) sb[tid] = b1[tid];
    __syncthreads();

#pragma unroll 1
    for (int grp = blockIdx.x; grp < NGRP1; grp += gridDim.x) {
        int g0 = grp * 16;
        {
            int m = w * 2 + sub;
            int d = g0 + m;
            if (f < FIN) {
                int dg = g_deg[d];
                int pd = (dg + 7) & ~7;
                int end = g_offs[d];
                float acc = 0.f;
#pragma unroll 1
                for (int e = end - pd; e < end; e += 4) {
                    int4 iv = *(const int4*)&g_csrc[e];
                    acc += g_xs[iv.x * FIN + f] + g_xs[iv.y * FIN + f]
                         + g_xs[iv.z * FIN + f] + g_xs[iv.w * FIN + f];
                }
                acc += g_xs[d * FIN + f];
                sU[m * FIN + f] = g_dinv[d] * acc;
            }
        }
        __syncthreads();
        {
            int c4 = (tid & 15) * 4;
            int m = tid >> 4;
            float4 acc = make_float4(sb[c4], sb[c4 + 1], sb[c4 + 2], sb[c4 + 3]);
#pragma unroll
            for (int k = 0; k < FIN; k++) {
                float a = sU[m * FIN + k];
                float4 wv = *(float4*)&sW[k * 64 + c4];
                acc.x += a * wv.x; acc.y += a * wv.y; acc.z += a * wv.z; acc.w += a * wv.w;
            }
            float s = g_dinv[g0 + m];
            float4 r;
            r.x = fmaxf(acc.x, 0.f) * s;
            r.y = fmaxf(acc.y, 0.f) * s;
            r.z = fmaxf(acc.z, 0.f) * s;
            r.w = fmaxf(acc.w, 0.f) * s;
            *(float4*)&g_fA[(g0 + m) * 64 + c4] = r;
        }
        __syncthreads();
    }
}

// ---------------- fused 64-wide aggregate + 64x64 GEMM (32 dsts/grp) ---------
// Group's CSR indices staged in smem; gather index fetch is LDS, feature
// gathers have 32 loads in flight per warp.
// SRCA: read g_fA else g_fB (write the other). SCALE: scale output by dinv.
// SCALE=false (last layer) also zeroes g_deg per group after its final read.
template <bool SRCA, bool SCALE>
__global__ void __launch_bounds__(256) k_layer64(const float* __restrict__ W,
                                                 const float* __restrict__ b) {
    __shared__ float sW[4096];
    __shared__ float sb[64];
    __shared__ __align__(16) float sA[2048];
    __shared__ __align__(16) int sidx[SIDX_CAP];
    const float* __restrict__ src = SRCA ? g_fA : g_fB;
    float* __restrict__ dst = SRCA ? g_fB : g_fA;
    int tid = threadIdx.x;
    int w = tid >> 5, lane = tid & 31;
    for (int i = tid; i < 4096; i += 256) sW[i] = W[i];
    if (tid < 64) sb[tid] = b[tid];
    __syncthreads();

#pragma unroll 1
    for (int grp = blockIdx.x; grp < NGRP64; grp += gridDim.x) {
        int g0 = grp * 32;
        // stage indices: [start0, endL) is the contiguous padded CSR range
        int start0 = g_offs[g0] - ((g_deg[g0] + 7) & ~7);
        int endL = g_offs[g0 + 31];
        int L = endL - start0;                 // multiple of 8, 32B-aligned base
        bool use_s = (L <= SIDX_CAP);          // uniform across block
        if (use_s) {
#pragma unroll 1
            for (int i = tid * 4; i < L; i += 1024)
                *(int4*)&sidx[i] = *(const int4*)&g_csrc[start0 + i];
        }
        __syncthreads();
        const int* ip = use_s ? (const int*)sidx - start0 : (const int*)g_csrc;
        // gather: warp handles 4 dsts, 8 edges per dst per round
        {
            int d[4]; int e[4], en[4]; u64t acc[4];
#pragma unroll
            for (int p = 0; p < 4; p++) {
                d[p] = g0 + w + p * 8;
                en[p] = g_offs[d[p]];
                int pd = (g_deg[d[p]] + 7) & ~7;
                e[p] = en[p] - pd;
                acc[p] = 0ULL;
            }
#pragma unroll 1
            for (;;) {
                bool any = false;
#pragma unroll
                for (int p = 0; p < 4; p++) {
                    if (e[p] < en[p]) {
                        any = true;
                        int4 i0 = *(const int4*)&ip[e[p]];
                        int4 i1 = *(const int4*)&ip[e[p] + 4];
                        u64t v0 = *(const u64t*)&src[i0.x * 64 + lane * 2];
                        u64t v1 = *(const u64t*)&src[i0.y * 64 + lane * 2];
                        u64t v2 = *(const u64t*)&src[i0.z * 64 + lane * 2];
                        u64t v3 = *(const u64t*)&src[i0.w * 64 + lane * 2];
                        u64t v4 = *(const u64t*)&src[i1.x * 64 + lane * 2];
                        u64t v5 = *(const u64t*)&src[i1.y * 64 + lane * 2];
                        u64t v6 = *(const u64t*)&src[i1.z * 64 + lane * 2];
                        u64t v7 = *(const u64t*)&src[i1.w * 64 + lane * 2];
                        acc[p] = add2(acc[p],
                                 add2(add2(add2(v0, v1), add2(v2, v3)),
                                      add2(add2(v4, v5), add2(v6, v7))));
                        e[p] += 8;
                    }
                }
                if (!any) break;
            }
#pragma unroll
            for (int p = 0; p < 4; p++) {
                acc[p] = add2(acc[p], *(const u64t*)&src[d[p] * 64 + lane * 2]);
                float2 r = unpack2(acc[p]);
                float di = g_dinv[d[p]];
                sA[(w + p * 8) * 64 + lane * 2]     = di * r.x;
                sA[(w + p * 8) * 64 + lane * 2 + 1] = di * r.y;
            }
        }
        __syncthreads();
        if (!SCALE) {                     // last layer: restore deg==0 invariant
            if (tid < 32) g_deg[g0 + tid] = 0;
        }
        // GEMM 32x64 @ 64x64 + bias + relu (+dinv) — 8 outputs/thread
        {
            int c4 = (tid & 15) * 4;
            int m = tid >> 4;                  // rows m and m+16
            float4 acc0 = make_float4(sb[c4], sb[c4 + 1], sb[c4 + 2], sb[c4 + 3]);
            float4 acc1 = acc0;
#pragma unroll
            for (int k4 = 0; k4 < 16; k4++) {
                float4 a0 = *(float4*)&sA[m * 64 + k4 * 4];
                float4 a1 = *(float4*)&sA[(m + 16) * 64 + k4 * 4];
                float4 wv;
                wv = *(float4*)&sW[(k4 * 4 + 0) * 64 + c4];
                acc0.x += a0.x * wv.x; acc0.y += a0.x * wv.y; acc0.z += a0.x * wv.z; acc0.w += a0.x * wv.w;
                acc1.x += a1.x * wv.x; acc1.y += a1.x * wv.y; acc1.z += a1.x * wv.z; acc1.w += a1.x * wv.w;
                wv = *(float4*)&sW[(k4 * 4 + 1) * 64 + c4];
                acc0.x += a0.y * wv.x; acc0.y += a0.y * wv.y; acc0.z += a0.y * wv.z; acc0.w += a0.y * wv.w;
                acc1.x += a1.y * wv.x; acc1.y += a1.y * wv.y; acc1.z += a1.y * wv.z; acc1.w += a1.y * wv.w;
                wv = *(float4*)&sW[(k4 * 4 + 2) * 64 + c4];
                acc0.x += a0.z * wv.x; acc0.y += a0.z * wv.y; acc0.z += a0.z * wv.z; acc0.w += a0.z * wv.w;
                acc1.x += a1.z * wv.x; acc1.y += a1.z * wv.y; acc1.z += a1.z * wv.z; acc1.w += a1.z * wv.w;
                wv = *(float4*)&sW[(k4 * 4 + 3) * 64 + c4];
                acc0.x += a0.w * wv.x; acc0.y += a0.w * wv.y; acc0.z += a0.w * wv.z; acc0.w += a0.w * wv.w;
                acc1.x += a1.w * wv.x; acc1.y += a1.w * wv.y; acc1.z += a1.w * wv.z; acc1.w += a1.w * wv.w;
            }
            float s0 = SCALE ? g_dinv[g0 + m] : 1.f;
            float s1 = SCALE ? g_dinv[g0 + m + 16] : 1.f;
            float4 r0, r1;
            r0.x = fmaxf(acc0.x, 0.f) * s0; r0.y = fmaxf(acc0.y, 0.f) * s0;
            r0.z = fmaxf(acc0.z, 0.f) * s0; r0.w = fmaxf(acc0.w, 0.f) * s0;
            r1.x = fmaxf(acc1.x, 0.f) * s1; r1.y = fmaxf(acc1.y, 0.f) * s1;
            r1.z = fmaxf(acc1.z, 0.f) * s1; r1.w = fmaxf(acc1.w, 0.f) * s1;
            *(float4*)&dst[(g0 + m) * 64 + c4] = r0;
            *(float4*)&dst[(g0 + m + 16) * 64 + c4] = r1;
        }
        __syncthreads();
    }
}

// ---------------- LSTM layer-0 input projection: outer-product tiling --------
// Tile = 32 rows x 256 gates; thread computes 8 rows x 4 gates (2 gate-pairs).
#define WGP_STRIDE 65
__global__ void __launch_bounds__(256) k_xproj(const float* __restrict__ Wih,
                                               const float* __restrict__ bih,
                                               const float* __restrict__ bhh) {
    extern __shared__ __align__(16) char smraw[];
    u64t* sWgp  = (u64t*)smraw;                  // 128 * 65 = 8320 u64t
    u64t* sxdup = sWgp + 128 * WGP_STRIDE;       // 32 * 64 = 2048 u64t
    u64t* sBgp  = sxdup + 2048;                  // 128 u64t
    int tid = threadIdx.x;
    int gq = tid & 63;        // gate-quad: gates 4gq..4gq+3
    int rq = tid >> 6;        // row-octet: rows 8rq..8rq+7

    for (int i = tid; i < 128 * 64; i += 256) {
        int gp = i >> 6, j = i & 63;
        sWgp[gp * WGP_STRIDE + j] = pack2(Wih[(2 * gp) * 64 + j], Wih[(2 * gp + 1) * 64 + j]);
    }
    if (tid < 128)
        sBgp[tid] = pack2(bih[2 * tid] + bhh[2 * tid], bih[2 * tid + 1] + bhh[2 * tid + 1]);
    __syncthreads();

    const u64t* wrow0 = &sWgp[(2 * gq) * WGP_STRIDE];       // 16B-aligned rows
    const u64t* wrow1 = &sWgp[(2 * gq + 1) * WGP_STRIDE];   // 8B-aligned only
    u64t bg0 = sBgp[2 * gq], bg1 = sBgp[2 * gq + 1];

#pragma unroll 1
    for (int tile = blockIdx.x; tile < NTILE; tile += gridDim.x) {
        int g0 = tile * 32;
#pragma unroll
        for (int k = 0; k < 2; k++) {
            int i4 = tid + k * 256;           // 512 float4 total
            int r = i4 >> 4, j4 = i4 & 15;
            float4 v = *(const float4*)&g_fB[(g0 + r) * 64 + j4 * 4];
            sxdup[r * 64 + j4 * 4 + 0] = pack2(v.x, v.x);
            sxdup[r * 64 + j4 * 4 + 1] = pack2(v.y, v.y);
            sxdup[r * 64 + j4 * 4 + 2] = pack2(v.z, v.z);
            sxdup[r * 64 + j4 * 4 + 3] = pack2(v.w, v.w);
        }
        __syncthreads();
        u64t acc[8][2];
#pragma unroll
        for (int r = 0; r < 8; r++) { acc[r][0] = bg0; acc[r][1] = bg1; }
#pragma unroll 4
        for (int j2 = 0; j2 < 32; j2++) {
            ulonglong2 w0 = *(const ulonglong2*)&wrow0[j2 * 2];   // aligned
            u64t w1x = wrow1[j2 * 2];                             // LDS.64 pair
            u64t w1y = wrow1[j2 * 2 + 1];
#pragma unroll
            for (int r = 0; r < 8; r++) {
                ulonglong2 xv = *(const ulonglong2*)&sxdup[(8 * rq + r) * 64 + j2 * 2];
                ffma2(acc[r][0], w0.x, xv.x);
                ffma2(acc[r][0], w0.y, xv.y);
                ffma2(acc[r][1], w1x, xv.x);
                ffma2(acc[r][1], w1y, xv.y);
            }
        }
        u64t* outp = (u64t*)g_xp;
#pragma unroll
        for (int r = 0; r < 8; r++) {
            ulonglong2 st;
            st.x = acc[r][0]; st.y = acc[r][1];
            *(ulonglong2*)&outp[(u64t)(g0 + 8 * rq + r) * 128 + 2 * gq] = st;
        }
        __syncthreads();
    }
}

// ---------------- fused 2-layer LSTM + output projection ---------------------
// Node-split layout: threads 0-127 own local nodes 0-6, threads 128-255 own
// nodes 7-13. Each thread computes TWO gates: ht and ht+128 (ht = tid & 127).
// Layer-0 weight rows live in registers; layer-1 weights in swizzled smem.
__device__ __forceinline__ float sigf(float x) { return 1.f / (1.f + __expf(-x)); }
__device__ __forceinline__ float tanhfast(float x) { return 1.f - 2.f / (__expf(2.f * x) + 1.f); }

__global__ void __launch_bounds__(256, 1) k_lstm(
    const float* __restrict__ Whh0,
    const float* __restrict__ Wih1, const float* __restrict__ Whh1,
    const float* __restrict__ bih1, const float* __restrict__ bhh1,
    const float* __restrict__ Wout, const float* __restrict__ bout,
    float* __restrict__ out)
{
    extern __shared__ float sm[];
    float* sWi1 = sm;                  // 16384 (swizzled)
    float* sW1  = sm + 16384;          // 16384 (swizzled)
    float* sh0  = sm + 32768;          // NB*64 = 896
    float* sh1  = sh0 + NB * 64;       // 896
    float* sg   = sh1 + NB * 64;       // NB*256 = 3584

    int tid = threadIdx.x;
    int ht   = tid & 127;              // gate-half index: gates ht and ht+128
    int half = tid >> 7;               // node half: 0 -> nodes 0-6, 1 -> 7-13
    for (int i = tid; i < NG * HID; i += 256) {
        int r = i >> 6, c = i & 63;
        int pos = r * 64 + (((c >> 2) ^ (r & 15)) << 2) + (c & 3);
        sWi1[pos] = Wih1[i];
        sW1[pos]  = Whh1[i];
    }
    for (int i = tid; i < NB * 64; i += 256) { sh0[i] = 0.f; sh1[i] = 0.f; }
    // layer-0 weight rows ht and ht+128 -> registers
    ulonglong2 wA[16], wB[16];
#pragma unroll
    for (int j4 = 0; j4 < 16; j4++) {
        wA[j4] = *(const ulonglong2*)&Whh0[ht * 64 + j4 * 4];
        wB[j4] = *(const ulonglong2*)&Whh0[(ht + 128) * 64 + j4 * 4];
    }
    u64t bA = pack2(bih1[ht] + bhh1[ht], 0.f);
    u64t bB = pack2(bih1[ht + 128] + bhh1[ht + 128], 0.f);
    bool gB_tanh = (ht < 64);          // gate ht+128 is 'g' (tanh) iff ht<64
    int wbaseA = ht * 64;
    int wbaseB = (ht + 128) * 64;
    int wrot = ht & 15;                // same rot for ht+128
    int nbase = half * 7;              // local node offset
    __syncthreads();

    int n0 = blockIdx.x * NB;
    float c0[4] = {0.f, 0.f, 0.f, 0.f};
    float c1[4] = {0.f, 0.f, 0.f, 0.f};

#pragma unroll 1
    for (int t = 0; t < WIN; t++) {
        // ---- layer 0 gates (7 nodes, 2 gates per thread) ----
        u64t accA[7], accB[7];
#pragma unroll
        for (int nn = 0; nn < 7; nn++) {
            int n = n0 + nbase + nn;
            int nc = (n < NODES) ? n : (NODES - 1);
            const float* xp = &g_xp[(u64t)(t * NODES + nc) * NG];
            accA[nn] = pack2(xp[ht], 0.f);
            accB[nn] = pack2(xp[ht + 128], 0.f);
        }
#pragma unroll 8
        for (int j4 = 0; j4 < 16; j4++) {
#pragma unroll
            for (int nn = 0; nn < 7; nn++) {
                ulonglong2 h = *(const ulonglong2*)&sh0[(nbase + nn) * 64 + j4 * 4];
                ffma2(accA[nn], wA[j4].x, h.x);
                ffma2(accA[nn], wA[j4].y, h.y);
                ffma2(accB[nn], wB[j4].x, h.x);
                ffma2(accB[nn], wB[j4].y, h.y);
            }
        }
#pragma unroll
        for (int nn = 0; nn < 7; nn++) {
            float vA = hsum2(accA[nn]);
            float vB = hsum2(accB[nn]);
            int g = (nbase + nn) * 256;
            sg[g + ht] = sigf(vA);                            // i or f
            sg[g + 128 + ht] = gB_tanh ? tanhfast(vB) : sigf(vB);  // g or o
        }
        __syncthreads();
#pragma unroll
        for (int r = 0; r < 4; r++) {
            int idx = tid + 256 * r;
            if (idx < NB * 64) {
                int nn = idx >> 6, e = idx & 63;
                float gi = sg[nn * 256 + e],       gf = sg[nn * 256 + 64 + e];
                float gg = sg[nn * 256 + 128 + e], go = sg[nn * 256 + 192 + e];
                c0[r] = gf * c0[r] + gi * gg;
                sh0[idx] = go * tanhfast(c0[r]);
            }
        }
        __syncthreads();
        // ---- layer 1 gates ----
#pragma unroll
        for (int nn = 0; nn < 7; nn++) { accA[nn] = bA; accB[nn] = bB; }
#pragma unroll 8
        for (int j4 = 0; j4 < 16; j4++) {
            int wo = (j4 ^ wrot) << 2;
            ulonglong2 wiA = *(const ulonglong2*)&sWi1[wbaseA + wo];
            ulonglong2 wiB = *(const ulonglong2*)&sWi1[wbaseB + wo];
            ulonglong2 whA = *(const ulonglong2*)&sW1[wbaseA + wo];
            ulonglong2 whB = *(const ulonglong2*)&sW1[wbaseB + wo];
#pragma unroll
            for (int nn = 0; nn < 7; nn++) {
                ulonglong2 h0 = *(const ulonglong2*)&sh0[(nbase + nn) * 64 + j4 * 4];
                ulonglong2 h1 = *(const ulonglong2*)&sh1[(nbase + nn) * 64 + j4 * 4];
                ffma2(accA[nn], wiA.x, h0.x);
                ffma2(accA[nn], wiA.y, h0.y);
                ffma2(accA[nn], whA.x, h1.x);
                ffma2(accA[nn], whA.y, h1.y);
                ffma2(accB[nn], wiB.x, h0.x);
                ffma2(accB[nn], wiB.y, h0.y);
                ffma2(accB[nn], whB.x, h1.x);
                ffma2(accB[nn], whB.y, h1.y);
            }
        }
#pragma unroll
        for (int nn = 0; nn < 7; nn++) {
            float vA = hsum2(accA[nn]);
            float vB = hsum2(accB[nn]);
            int g = (nbase + nn) * 256;
            sg[g + ht] = sigf(vA);
            sg[g + 128 + ht] = gB_tanh ? tanhfast(vB) : sigf(vB);
        }
        __syncthreads();
#pragma unroll
        for (int r = 0; r < 4; r++) {
            int idx = tid + 256 * r;
            if (idx < NB * 64) {
                int nn = idx >> 6, e = idx & 63;
                float gi = sg[nn * 256 + e],       gf = sg[nn * 256 + 64 + e];
                float gg = sg[nn * 256 + 128 + e], go = sg[nn * 256 + 192 + e];
                c1[r] = gf * c1[r] + gi * gg;
                sh1[idx] = go * tanhfast(c1[r]);
            }
        }
        __syncthreads();
    }
    // ---- output projection: 14 nodes x 96 outputs ----
#pragma unroll 1
    for (int i = tid; i < NB * 96; i += 256) {
        int nn = i / 96, o = i - nn * 96;
        int n = n0 + nn;
        if (n < NODES) {
            float a = bout[o];
#pragma unroll
            for (int k = 0; k < 64; k++)
                a += sh1[nn * 64 + k] * Wout[k * 96 + o];
            out[n * 96 + o] = a;
        }
    }
}

// ---------------- launcher ---------------------------------------------------
extern "C" void kernel_launch(void* const* d_in, const int* in_sizes, int n_in,
                              void* d_out, int out_size) {
    const float* x    = (const float*)d_in[0];
    const int*   ei   = (const int*)  d_in[1];
    const float* W1   = (const float*)d_in[2];
    const float* b1   = (const float*)d_in[3];
    const float* W2   = (const float*)d_in[4];
    const float* b2   = (const float*)d_in[5];
    const float* W3   = (const float*)d_in[6];
    const float* b3   = (const float*)d_in[7];
    const float* W4   = (const float*)d_in[8];
    const float* b4   = (const float*)d_in[9];
    const float* Wih0 = (const float*)d_in[10];
    const float* Whh0 = (const float*)d_in[11];
    const float* bih0 = (const float*)d_in[12];
    const float* bhh0 = (const float*)d_in[13];
    const float* Wih1 = (const float*)d_in[14];
    const float* Whh1 = (const float*)d_in[15];
    const float* bih1 = (const float*)d_in[16];
    const float* bhh1 = (const float*)d_in[17];
    const float* Wout = (const float*)d_in[18];
    const float* bout = (const float*)d_in[19];
    float* out = (float*)d_out;

    const int XP_SMEM   = (128 * WGP_STRIDE + 2048 + 128) * 8;                // 83968
    const int LSTM_SMEM = (2 * 16384 + NB * 64 * 2 + NB * 256) * 4;           // 152576
    cudaFuncSetAttribute(k_xproj, cudaFuncAttributeMaxDynamicSharedMemorySize, XP_SMEM);
    cudaFuncSetAttribute(k_lstm,  cudaFuncAttributeMaxDynamicSharedMemorySize, LSTM_SMEM);

    // graph preprocessing (separate launches; g_deg zeroed by last GCN layer)
    k_count<<<3000, 256>>>(ei);
    k_scanA<<<188, 256>>>();
    k_scanC<<<188, 256>>>(x);
    k_fill<<<3000, 256>>>(ei);

    // GCN stack (fused aggregate + GEMM, double-buffered A/B)
    // Grids sized to exact 1-wave multiples of 148 SMs (4/SM for the layer
    // kernels, warp-limited) to kill partial-wave occupancy loss.
    k_layer1<<<GRID_L1, 256>>>(W1, b1);                     // xs -> A
    k_layer64<true,  true ><<<GRID_L64, 256>>>(W2, b2);     // A -> B
    k_layer64<false, true ><<<GRID_L64, 256>>>(W3, b3);     // B -> A
    k_layer64<true,  false><<<GRID_L64, 256>>>(W4, b4);     // A -> B (zeroes g_deg)

    // LSTM
    k_xproj<<<GRID_XP, 256, XP_SMEM>>>(Wih0, bih0, bhh0);   // 2/SM ceiling
    k_lstm<<<NBLK, 256, LSTM_SMEM>>>(Whh0, Wih1, Whh1, bih1, bhh1, Wout, bout, out);
}